// round 9
// baseline (speedup 1.0000x reference)
#include <cuda_runtime.h>
#include <cuda_bf16.h>
#include <cstdint>
#include <cstddef>

#define WIN 7
#define NTOK 49
#define NH 16
#define HD 32
#define CDIM 512
#define BATCH 2048
#define M_TOT (BATCH * NTOK)   // 100352 = 784 * 128
#define KEFF 1536              // 3 * 512 (hi|lo|hi concat)

// ---------------- scratch (static device globals; no allocations) ----------------
__device__ float g_qkv [(size_t)M_TOT * 3 * CDIM];          // 616 MB
__device__ __nv_bfloat16 g_A3 [(size_t)M_TOT * KEFF];       // 308 MB
__device__ __nv_bfloat16 g_A3b[(size_t)M_TOT * KEFF];       // 308 MB
__device__ __nv_bfloat16 g_B3 [(size_t)3 * CDIM * KEFF];    // 4.7 MB

// =====================================================================
// helpers
// =====================================================================
__device__ __forceinline__ uint32_t smem_u32(const void* p) {
    uint32_t a;
    asm("{ .reg .u64 t; cvta.to.shared.u64 t, %1; cvt.u32.u64 %0, t; }" : "=r"(a) : "l"(p));
    return a;
}
__device__ __forceinline__ void cp16(uint32_t s, const void* g) {
    asm volatile("cp.async.cg.shared.global [%0], [%1], 16;" :: "r"(s), "l"(g));
}
__device__ __forceinline__ uint32_t pack_bf16(__nv_bfloat16 a, __nv_bfloat16 b) {
    return ((uint32_t)__bfloat16_as_ushort(b) << 16) | __bfloat16_as_ushort(a);
}
__device__ __forceinline__ void split1(float v, __nv_bfloat16& h, __nv_bfloat16& l) {
    h = __float2bfloat16_rn(v);
    l = __float2bfloat16_rn(v - __bfloat162float(h));
}

// =====================================================================
// split: mode 0 (A-side): [hi | lo | hi]   mode 1 (B-side): [hi | hi | lo]
// =====================================================================
__global__ void split3_kernel(const float* __restrict__ src,
                              __nv_bfloat16* __restrict__ dst,
                              int n4, int mode)
{
    int i = blockIdx.x * blockDim.x + threadIdx.x;
    if (i >= n4) return;
    const int row = i >> 7;
    const int col = (i & 127) * 4;
    float4 v = ((const float4*)src)[i];

    __nv_bfloat16 h0, h1, h2, h3, l0, l1, l2, l3;
    split1(v.x, h0, l0); split1(v.y, h1, l1);
    split1(v.z, h2, l2); split1(v.w, h3, l3);

    uint32_t hA = pack_bf16(h0, h1), hB = pack_bf16(h2, h3);
    uint32_t lA = pack_bf16(l0, l1), lB = pack_bf16(l2, l3);

    uint32_t* base = (uint32_t*)(dst + (size_t)row * KEFF + col);
    if (mode == 0) {
        base[0] = hA;   base[1] = hB;
        base[256] = lA; base[257] = lB;
        base[512] = hA; base[513] = hB;
    } else {
        base[0] = hA;   base[1] = hB;
        base[256] = hA; base[257] = hB;
        base[512] = lA; base[513] = lB;
    }
}

// =====================================================================
// BF16 GEMM via mma.sync:  C[M,N] = A3[M,1536] * B3[N,1536]^T + bias[N]
// CTA tile 128x256, BK=64, 3-stage cp.async, 256 threads (8 warps 2x4),
// warp tile 64x64.
// split_out=0: fp32 Cf[M,N].  split_out=1: bf16 hi|lo|hi Cs[M,1536].
// =====================================================================
#define BKB 64
#define NKIT (KEFF / BKB)              // 24
#define ST_A (128 * BKB * 2)           // 16384
#define ST_B (256 * BKB * 2)           // 32768
#define STAGE_BYTES (ST_A + ST_B)      // 49152
#define GEMM_SMEM (3 * STAGE_BYTES)    // 147456

__global__ void __launch_bounds__(256, 1)
gemm_bf16x3(const __nv_bfloat16* __restrict__ A,
            const __nv_bfloat16* __restrict__ B,
            const float* __restrict__ bias,
            float* __restrict__ Cf,
            __nv_bfloat16* __restrict__ Cs,
            int N, int split_out)
{
    extern __shared__ char smem[];
    const uint32_t sb = smem_u32(smem);
    const int tid  = threadIdx.x;
    const int lane = tid & 31;
    const int wid  = tid >> 5;
    const int wm   = wid >> 2;     // 0..1  (M 64-blocks)
    const int wn   = wid & 3;      // 0..3  (N 64-blocks)

    const __nv_bfloat16* Ag = A + (size_t)blockIdx.y * 128 * KEFF;
    const __nv_bfloat16* Bg = B + (size_t)blockIdx.x * 256 * KEFF;

    const int lr = tid >> 3;       // 0..31
    const int lc = tid & 7;        // 16B chunk 0..7

    auto load_stage = [&](int kt, int slot) {
        const uint32_t base = sb + (uint32_t)slot * STAGE_BYTES;
        const int kof = kt * BKB;
        const uint32_t socol = (uint32_t)((lc ^ (lr & 7)) << 4);
#pragma unroll
        for (int i = 0; i < 4; i++) {
            const int r = lr + i * 32;
            const uint32_t so = (uint32_t)r * 128 + socol;
            cp16(base + so, Ag + (size_t)r * KEFF + kof + lc * 8);
        }
#pragma unroll
        for (int i = 0; i < 8; i++) {
            const int r = lr + i * 32;
            const uint32_t so = (uint32_t)r * 128 + socol;
            cp16(base + ST_A + so, Bg + (size_t)r * KEFF + kof + lc * 8);
        }
    };

    float acc[4][8][4];
#pragma unroll
    for (int a = 0; a < 4; a++)
#pragma unroll
        for (int b = 0; b < 8; b++)
#pragma unroll
            for (int c = 0; c < 4; c++) acc[a][b][c] = 0.f;

    load_stage(0, 0); asm volatile("cp.async.commit_group;" ::: "memory");
    load_stage(1, 1); asm volatile("cp.async.commit_group;" ::: "memory");

    // A ldmatrix.x4: 16x16 tile at (wm*64 + im*16, kk*16)
    const int rA0 = wm * 64 + (lane & 15);
    const int cAh = lane >> 4;                 // 0..1
    // B ldmatrix.x4 (paired): lanes' group g=lane>>3: matrix (inp*2 + (g>>1), kk half g&1)
    const int rB0 = wn * 64 + (lane & 7);
    const int gB  = lane >> 3;                 // 0..3
    const int rBo = (gB >> 1) * 8;             // +8 rows for second in of pair
    const int cBh = gB & 1;

    for (int kt = 0; kt < NKIT; kt++) {
        asm volatile("cp.async.wait_group 1;" ::: "memory");
        __syncthreads();
        if (kt + 2 < NKIT) load_stage(kt + 2, (kt + 2) % 3);
        asm volatile("cp.async.commit_group;" ::: "memory");

        const uint32_t base = sb + (uint32_t)(kt % 3) * STAGE_BYTES;
#pragma unroll
        for (int kk = 0; kk < 4; kk++) {
            uint32_t afr[4][4];
#pragma unroll
            for (int im = 0; im < 4; im++) {
                const int r = rA0 + im * 16;
                const uint32_t addr = base + (uint32_t)r * 128 +
                    (uint32_t)(((2 * kk + cAh) ^ (r & 7)) << 4);
                asm volatile("ldmatrix.sync.aligned.m8n8.x4.shared.b16 {%0,%1,%2,%3}, [%4];"
                    : "=r"(afr[im][0]), "=r"(afr[im][1]), "=r"(afr[im][2]), "=r"(afr[im][3])
                    : "r"(addr));
            }
            uint32_t bfr[8][2];
#pragma unroll
            for (int ip = 0; ip < 4; ip++) {         // pair of in: 2*ip, 2*ip+1
                const int r = rB0 + ip * 16 + rBo;
                const uint32_t addr = base + ST_A + (uint32_t)r * 128 +
                    (uint32_t)(((2 * kk + cBh) ^ (r & 7)) << 4);
                asm volatile("ldmatrix.sync.aligned.m8n8.x4.shared.b16 {%0,%1,%2,%3}, [%4];"
                    : "=r"(bfr[2*ip][0]), "=r"(bfr[2*ip][1]),
                      "=r"(bfr[2*ip+1][0]), "=r"(bfr[2*ip+1][1])
                    : "r"(addr));
            }
#pragma unroll
            for (int im = 0; im < 4; im++)
#pragma unroll
                for (int in = 0; in < 8; in++) {
                    asm volatile(
                        "mma.sync.aligned.m16n8k16.row.col.f32.bf16.bf16.f32 "
                        "{%0,%1,%2,%3}, {%4,%5,%6,%7}, {%8,%9}, {%0,%1,%2,%3};"
                        : "+f"(acc[im][in][0]), "+f"(acc[im][in][1]),
                          "+f"(acc[im][in][2]), "+f"(acc[im][in][3])
                        : "r"(afr[im][0]), "r"(afr[im][1]), "r"(afr[im][2]), "r"(afr[im][3]),
                          "r"(bfr[in][0]), "r"(bfr[in][1]));
                }
        }
    }

    // ---- epilogue ----
    const int mBase = blockIdx.y * 128 + wm * 64;
    const int nBase = blockIdx.x * 256 + wn * 64;
    const int rr = lane >> 2;
    const int cc = (lane & 3) * 2;

    if (!split_out) {
#pragma unroll
        for (int im = 0; im < 4; im++)
#pragma unroll
            for (int in = 0; in < 8; in++) {
                const int row = mBase + im * 16 + rr;
                const int col = nBase + in * 8 + cc;
                const float bx = bias[col], by = bias[col + 1];
                *(float2*)(Cf + (size_t)row * N + col) =
                    make_float2(acc[im][in][0] + bx, acc[im][in][1] + by);
                *(float2*)(Cf + (size_t)(row + 8) * N + col) =
                    make_float2(acc[im][in][2] + bx, acc[im][in][3] + by);
            }
    } else {
#pragma unroll
        for (int im = 0; im < 4; im++)
#pragma unroll
            for (int in = 0; in < 8; in++) {
                const int row = mBase + im * 16 + rr;
                const int col = nBase + in * 8 + cc;
                const float bx = bias[col], by = bias[col + 1];
                float v0 = acc[im][in][0] + bx, v1 = acc[im][in][1] + by;
                float v2 = acc[im][in][2] + bx, v3 = acc[im][in][3] + by;
                __nv_bfloat16 h0, h1, h2, h3, l0, l1, l2, l3;
                split1(v0, h0, l0); split1(v1, h1, l1);
                split1(v2, h2, l2); split1(v3, h3, l3);
                uint32_t* p0 = (uint32_t*)(Cs + (size_t)row * KEFF + col);
                p0[0]   = pack_bf16(h0, h1);
                p0[256] = pack_bf16(l0, l1);
                p0[512] = pack_bf16(h0, h1);
                uint32_t* p1 = (uint32_t*)(Cs + (size_t)(row + 8) * KEFF + col);
                p1[0]   = pack_bf16(h2, h3);
                p1[256] = pack_bf16(l2, l3);
                p1[512] = pack_bf16(h2, h3);
            }
    }
}

// =====================================================================
// fused windowed attention (register-blocked), writes bf16 hi|lo|hi split
// =====================================================================
__global__ __launch_bounds__(256)
void attn_kernel(const float* __restrict__ qkv,
                 const float* __restrict__ bias_table,
                 const int*   __restrict__ rel_idx,
                 __nv_bfloat16* __restrict__ outs)   // [M_TOT, 1536]
{
    const int b  = blockIdx.x;
    const int hh = blockIdx.y;
    const int tid = threadIdx.x;

    __shared__ float qs[NTOK][HD + 1];
    __shared__ float ks[NTOK][HD + 1];
    __shared__ float vs[NTOK][HD + 1];
    __shared__ float sc[NTOK][NTOK + 1];

    const size_t rowbase = (size_t)b * NTOK;

    for (int idx = tid; idx < NTOK * HD; idx += 256) {
        const int i = idx >> 5, d = idx & 31;
        const size_t base = (rowbase + i) * (3 * CDIM) + hh * HD + d;
        qs[i][d] = qkv[base] * 0.25f;
        ks[i][d] = qkv[base + CDIM];
        vs[i][d] = qkv[base + 2 * CDIM];
    }
    __syncthreads();

    for (int it = tid; it < 625; it += 256) {
        const int pi = it / 25, pj = it - pi * 25;
        const int i0 = 2 * pi, j0 = 2 * pj;
        const int i1 = (i0 + 1 < NTOK) ? i0 + 1 : i0;
        const int j1 = (j0 + 1 < NTOK) ? j0 + 1 : j0;
        float s00 = 0.f, s01 = 0.f, s10 = 0.f, s11 = 0.f;
#pragma unroll
        for (int d = 0; d < HD; d++) {
            const float qa = qs[i0][d], qb = qs[i1][d];
            const float ka = ks[j0][d], kb = ks[j1][d];
            s00 = fmaf(qa, ka, s00); s01 = fmaf(qa, kb, s01);
            s10 = fmaf(qb, ka, s10); s11 = fmaf(qb, kb, s11);
        }
        sc[i0][j0] = s00 + bias_table[rel_idx[i0 * NTOK + j0] * NH + hh];
        if (j0 + 1 < NTOK)
            sc[i0][j1] = s01 + bias_table[rel_idx[i0 * NTOK + j1] * NH + hh];
        if (i0 + 1 < NTOK) {
            sc[i1][j0] = s10 + bias_table[rel_idx[i1 * NTOK + j0] * NH + hh];
            if (j0 + 1 < NTOK)
                sc[i1][j1] = s11 + bias_table[rel_idx[i1 * NTOK + j1] * NH + hh];
        }
    }
    __syncthreads();

    if (tid < NTOK) {
        float m = -1e30f;
#pragma unroll 7
        for (int j = 0; j < NTOK; j++) m = fmaxf(m, sc[tid][j]);
        float sum = 0.f;
#pragma unroll 7
        for (int j = 0; j < NTOK; j++) {
            const float e = __expf(sc[tid][j] - m);
            sc[tid][j] = e;
            sum += e;
        }
        const float inv = 1.f / sum;
#pragma unroll 7
        for (int j = 0; j < NTOK; j++) sc[tid][j] *= inv;
    }
    __syncthreads();

    if (tid < 200) {
        const int pi = tid >> 3, pd = tid & 7;
        const int i0 = 2 * pi, d0 = 4 * pd;
        const int i1 = (i0 + 1 < NTOK) ? i0 + 1 : i0;
        float a0 = 0.f, a1 = 0.f, a2 = 0.f, a3 = 0.f;
        float b0 = 0.f, b1 = 0.f, b2 = 0.f, b3 = 0.f;
#pragma unroll
        for (int j = 0; j < NTOK; j++) {
            const float pa = sc[i0][j], pb = sc[i1][j];
            const float v0 = vs[j][d0], v1 = vs[j][d0 + 1];
            const float v2 = vs[j][d0 + 2], v3 = vs[j][d0 + 3];
            a0 = fmaf(pa, v0, a0); a1 = fmaf(pa, v1, a1);
            a2 = fmaf(pa, v2, a2); a3 = fmaf(pa, v3, a3);
            b0 = fmaf(pb, v0, b0); b1 = fmaf(pb, v1, b1);
            b2 = fmaf(pb, v2, b2); b3 = fmaf(pb, v3, b3);
        }
        {
            __nv_bfloat16 h0, h1, h2, h3, l0, l1, l2, l3;
            split1(a0, h0, l0); split1(a1, h1, l1);
            split1(a2, h2, l2); split1(a3, h3, l3);
            uint32_t* p = (uint32_t*)(outs + (rowbase + i0) * KEFF + hh * HD + d0);
            p[0] = pack_bf16(h0, h1);   p[1] = pack_bf16(h2, h3);
            p[256] = pack_bf16(l0, l1); p[257] = pack_bf16(l2, l3);
            p[512] = pack_bf16(h0, h1); p[513] = pack_bf16(h2, h3);
        }
        if (i0 + 1 < NTOK) {
            __nv_bfloat16 h0, h1, h2, h3, l0, l1, l2, l3;
            split1(b0, h0, l0); split1(b1, h1, l1);
            split1(b2, h2, l2); split1(b3, h3, l3);
            uint32_t* p = (uint32_t*)(outs + (rowbase + i1) * KEFF + hh * HD + d0);
            p[0] = pack_bf16(h0, h1);   p[1] = pack_bf16(h2, h3);
            p[256] = pack_bf16(l0, l1); p[257] = pack_bf16(l2, l3);
            p[512] = pack_bf16(h0, h1); p[513] = pack_bf16(h2, h3);
        }
    }
}

// =====================================================================
// launch
// =====================================================================
static inline void launch_split(const float* src, __nv_bfloat16* dst,
                                size_t nelem, int mode) {
    const int n4 = (int)(nelem / 4);
    split3_kernel<<<(n4 + 255) / 256, 256>>>(src, dst, n4, mode);
}

extern "C" void kernel_launch(void* const* d_in, const int* in_sizes, int n_in,
                              void* d_out, int out_size)
{
    const float* x          = (const float*)d_in[0];
    const float* w_qkv      = (const float*)d_in[1];
    const float* b_qkv      = (const float*)d_in[2];
    const float* w_gamma    = (const float*)d_in[3];
    const float* b_gamma    = (const float*)d_in[4];
    const float* w_proj     = (const float*)d_in[5];
    const float* b_proj     = (const float*)d_in[6];
    const float* bias_table = (const float*)d_in[7];
    const int*   rel_idx    = (const int*)d_in[8];
    float* out = (float*)d_out;

    float* qkv_buf;
    __nv_bfloat16 *A3, *A3b, *B3;
    cudaGetSymbolAddress((void**)&qkv_buf, g_qkv);
    cudaGetSymbolAddress((void**)&A3,  g_A3);
    cudaGetSymbolAddress((void**)&A3b, g_A3b);
    cudaGetSymbolAddress((void**)&B3,  g_B3);

    cudaFuncSetAttribute(gemm_bf16x3, cudaFuncAttributeMaxDynamicSharedMemorySize, GEMM_SMEM);

    // 1) qkv = x @ w_qkv^T + b_qkv   [100352, 1536] fp32
    launch_split(x, A3, (size_t)M_TOT * CDIM, 0);
    launch_split(w_qkv, B3, (size_t)3 * CDIM * CDIM, 1);
    {
        dim3 grid(3 * CDIM / 256, M_TOT / 128);
        gemm_bf16x3<<<grid, 256, GEMM_SMEM>>>(A3, B3, b_qkv, qkv_buf, nullptr, 3 * CDIM, 0);
    }
    // 2) attention -> A3b (bf16 split layout)
    {
        dim3 grid(BATCH, NH);
        attn_kernel<<<grid, 256>>>(qkv_buf, bias_table, rel_idx, A3b);
    }
    // 3) gamma -> A3 (bf16 split layout)
    launch_split(w_gamma, B3, (size_t)CDIM * CDIM, 1);
    {
        dim3 grid(CDIM / 256, M_TOT / 128);
        gemm_bf16x3<<<grid, 256, GEMM_SMEM>>>(A3b, B3, b_gamma, nullptr, A3, CDIM, 1);
    }
    // 4) out = gamma_out @ w_proj^T + b_proj -> d_out fp32
    launch_split(w_proj, B3, (size_t)CDIM * CDIM, 1);
    {
        dim3 grid(CDIM / 256, M_TOT / 128);
        gemm_bf16x3<<<grid, 256, GEMM_SMEM>>>(A3, B3, b_proj, out, nullptr, CDIM, 0);
    }
}

// round 10
// speedup vs baseline: 1.3159x; 1.3159x over previous
#include <cuda_runtime.h>
#include <cuda_fp16.h>
#include <cstdint>
#include <cstddef>

#define WIN 7
#define NTOK 49
#define NH 16
#define HD 32
#define CDIM 512
#define BATCH 2048
#define M_TOT (BATCH * NTOK)   // 100352 = 784 * 128
#define KEFF 1024              // 2 * 512 (hi|lo concat)

// ---------------- scratch (static device globals; no allocations) ----------------
__device__ float g_qkv [(size_t)M_TOT * 3 * CDIM];     // 616 MB
__device__ __half g_A3 [(size_t)M_TOT * KEFF];         // 205 MB
__device__ __half g_A3b[(size_t)M_TOT * KEFF];         // 205 MB
__device__ __half g_B3 [(size_t)3 * CDIM * KEFF];      // 3.1 MB

// =====================================================================
// helpers
// =====================================================================
__device__ __forceinline__ uint32_t smem_u32(const void* p) {
    uint32_t a;
    asm("{ .reg .u64 t; cvta.to.shared.u64 t, %1; cvt.u32.u64 %0, t; }" : "=r"(a) : "l"(p));
    return a;
}
__device__ __forceinline__ void cp16(uint32_t s, const void* g) {
    asm volatile("cp.async.cg.shared.global [%0], [%1], 16;" :: "r"(s), "l"(g));
}
__device__ __forceinline__ uint32_t pack_h(__half a, __half b) {
    return ((uint32_t)__half_as_ushort(b) << 16) | __half_as_ushort(a);
}
__device__ __forceinline__ void split1(float v, __half& h, __half& l) {
    h = __float2half_rn(v);
    l = __float2half_rn(v - __half2float(h));
}

// =====================================================================
// split: src [rows, 512] fp32 -> dst [rows, 1024] fp16.
// mode 0 (A-side): [hi | lo]    mode 1 (B-side): [hi | hi]
// =====================================================================
__global__ void split2_kernel(const float* __restrict__ src,
                              __half* __restrict__ dst,
                              int n4, int mode)
{
    int i = blockIdx.x * blockDim.x + threadIdx.x;
    if (i >= n4) return;
    const int row = i >> 7;
    const int col = (i & 127) * 4;
    float4 v = ((const float4*)src)[i];

    __half h0, h1, h2, h3, l0, l1, l2, l3;
    split1(v.x, h0, l0); split1(v.y, h1, l1);
    split1(v.z, h2, l2); split1(v.w, h3, l3);

    uint32_t hA = pack_h(h0, h1), hB = pack_h(h2, h3);

    uint32_t* base = (uint32_t*)(dst + (size_t)row * KEFF + col);
    base[0] = hA; base[1] = hB;
    if (mode == 0) {
        base[256] = pack_h(l0, l1); base[257] = pack_h(l2, l3);
    } else {
        base[256] = hA; base[257] = hB;
    }
}

// =====================================================================
// FP16 GEMM via mma.sync:  C[M,N] = A2[M,1024] * B2[N,1024]^T + bias[N]
// CTA tile 128x128, BK=64, 3-stage cp.async, 256 threads (8 warps 2x4),
// warp tile 64x32.  (R7 geometry, 2 CTA/SM.)
// split_out=0: fp32 Cf[M,N].  split_out=1: fp16 hi|lo Cs[M,1024].
// =====================================================================
#define BKB 64
#define NKIT (KEFF / BKB)            // 16
#define STAGE_A (128 * BKB * 2)      // 16384
#define STAGE_BYTES (2 * STAGE_A)    // 32768 (A then B)
#define GEMM_SMEM (3 * STAGE_BYTES)  // 98304

__global__ void __launch_bounds__(256)
gemm_fp16x2(const __half* __restrict__ A,
            const __half* __restrict__ B,
            const float* __restrict__ bias,
            float* __restrict__ Cf,
            __half* __restrict__ Cs,
            int N, int split_out)
{
    extern __shared__ char smem[];
    const uint32_t sb = smem_u32(smem);
    const int tid  = threadIdx.x;
    const int lane = tid & 31;
    const int wid  = tid >> 5;
    const int wm   = wid >> 2;
    const int wn   = wid & 3;

    const __half* Ag = A + (size_t)blockIdx.y * 128 * KEFF;
    const __half* Bg = B + (size_t)blockIdx.x * 128 * KEFF;

    const int lr = tid >> 3;
    const int lc = tid & 7;

    auto load_stage = [&](int kt, int slot) {
        const uint32_t base = sb + (uint32_t)slot * STAGE_BYTES;
        const int kof = kt * BKB;
#pragma unroll
        for (int i = 0; i < 4; i++) {
            const int r = lr + i * 32;
            const uint32_t so = (uint32_t)r * 128 + (uint32_t)((lc ^ (r & 7)) << 4);
            cp16(base + so,           Ag + (size_t)r * KEFF + kof + lc * 8);
            cp16(base + STAGE_A + so, Bg + (size_t)r * KEFF + kof + lc * 8);
        }
    };

    float acc[4][4][4];
#pragma unroll
    for (int a = 0; a < 4; a++)
#pragma unroll
        for (int b = 0; b < 4; b++)
#pragma unroll
            for (int c = 0; c < 4; c++) acc[a][b][c] = 0.f;

    load_stage(0, 0); asm volatile("cp.async.commit_group;" ::: "memory");
    load_stage(1, 1); asm volatile("cp.async.commit_group;" ::: "memory");

    const int rA0 = wm * 64 + (lane & 15);
    const int cAh = lane >> 4;
    const int rB0 = wn * 32 + (lane & 7);
    const int cBh = (lane >> 3) & 1;

    for (int kt = 0; kt < NKIT; kt++) {
        asm volatile("cp.async.wait_group 1;" ::: "memory");
        __syncthreads();
        if (kt + 2 < NKIT) load_stage(kt + 2, (kt + 2) % 3);
        asm volatile("cp.async.commit_group;" ::: "memory");

        const uint32_t base = sb + (uint32_t)(kt % 3) * STAGE_BYTES;
#pragma unroll
        for (int kk = 0; kk < 4; kk++) {
            uint32_t afr[4][4];
#pragma unroll
            for (int im = 0; im < 4; im++) {
                const int r = rA0 + im * 16;
                const uint32_t addr = base + (uint32_t)r * 128 +
                    (uint32_t)(((2 * kk + cAh) ^ (r & 7)) << 4);
                asm volatile("ldmatrix.sync.aligned.m8n8.x4.shared.b16 {%0,%1,%2,%3}, [%4];"
                    : "=r"(afr[im][0]), "=r"(afr[im][1]), "=r"(afr[im][2]), "=r"(afr[im][3])
                    : "r"(addr));
            }
            uint32_t bfr[4][2];
#pragma unroll
            for (int in = 0; in < 4; in++) {
                const int r = rB0 + in * 8;
                const uint32_t addr = base + STAGE_A + (uint32_t)r * 128 +
                    (uint32_t)(((2 * kk + cBh) ^ (r & 7)) << 4);
                asm volatile("ldmatrix.sync.aligned.m8n8.x2.shared.b16 {%0,%1}, [%2];"
                    : "=r"(bfr[in][0]), "=r"(bfr[in][1]) : "r"(addr));
            }
#pragma unroll
            for (int im = 0; im < 4; im++)
#pragma unroll
                for (int in = 0; in < 4; in++) {
                    asm volatile(
                        "mma.sync.aligned.m16n8k16.row.col.f32.f16.f16.f32 "
                        "{%0,%1,%2,%3}, {%4,%5,%6,%7}, {%8,%9}, {%0,%1,%2,%3};"
                        : "+f"(acc[im][in][0]), "+f"(acc[im][in][1]),
                          "+f"(acc[im][in][2]), "+f"(acc[im][in][3])
                        : "r"(afr[im][0]), "r"(afr[im][1]), "r"(afr[im][2]), "r"(afr[im][3]),
                          "r"(bfr[in][0]), "r"(bfr[in][1]));
                }
        }
    }

    // ---- epilogue ----
    const int mBase = blockIdx.y * 128 + wm * 64;
    const int nBase = blockIdx.x * 128 + wn * 32;
    const int rr = lane >> 2;
    const int cc = (lane & 3) * 2;

    if (!split_out) {
#pragma unroll
        for (int im = 0; im < 4; im++)
#pragma unroll
            for (int in = 0; in < 4; in++) {
                const int row = mBase + im * 16 + rr;
                const int col = nBase + in * 8 + cc;
                const float bx = bias[col], by = bias[col + 1];
                *(float2*)(Cf + (size_t)row * N + col) =
                    make_float2(acc[im][in][0] + bx, acc[im][in][1] + by);
                *(float2*)(Cf + (size_t)(row + 8) * N + col) =
                    make_float2(acc[im][in][2] + bx, acc[im][in][3] + by);
            }
    } else {
#pragma unroll
        for (int im = 0; im < 4; im++)
#pragma unroll
            for (int in = 0; in < 4; in++) {
                const int row = mBase + im * 16 + rr;
                const int col = nBase + in * 8 + cc;
                const float bx = bias[col], by = bias[col + 1];
                float v0 = acc[im][in][0] + bx, v1 = acc[im][in][1] + by;
                float v2 = acc[im][in][2] + bx, v3 = acc[im][in][3] + by;
                __half h0, h1, h2, h3, l0, l1, l2, l3;
                split1(v0, h0, l0); split1(v1, h1, l1);
                split1(v2, h2, l2); split1(v3, h3, l3);
                uint32_t* p0 = (uint32_t*)(Cs + (size_t)row * KEFF + col);
                p0[0]   = pack_h(h0, h1);
                p0[256] = pack_h(l0, l1);
                uint32_t* p1 = (uint32_t*)(Cs + (size_t)(row + 8) * KEFF + col);
                p1[0]   = pack_h(h2, h3);
                p1[256] = pack_h(l2, l3);
            }
    }
}

// =====================================================================
// fused windowed attention (register-blocked), writes fp16 hi|lo split
// =====================================================================
__global__ __launch_bounds__(256)
void attn_kernel(const float* __restrict__ qkv,
                 const float* __restrict__ bias_table,
                 const int*   __restrict__ rel_idx,
                 __half* __restrict__ outs)   // [M_TOT, 1024]
{
    const int b  = blockIdx.x;
    const int hh = blockIdx.y;
    const int tid = threadIdx.x;

    __shared__ float qs[NTOK][HD + 1];
    __shared__ float ks[NTOK][HD + 1];
    __shared__ float vs[NTOK][HD + 1];
    __shared__ float sc[NTOK][NTOK + 1];

    const size_t rowbase = (size_t)b * NTOK;

    for (int idx = tid; idx < NTOK * HD; idx += 256) {
        const int i = idx >> 5, d = idx & 31;
        const size_t base = (rowbase + i) * (3 * CDIM) + hh * HD + d;
        qs[i][d] = qkv[base] * 0.25f;
        ks[i][d] = qkv[base + CDIM];
        vs[i][d] = qkv[base + 2 * CDIM];
    }
    __syncthreads();

    for (int it = tid; it < 625; it += 256) {
        const int pi = it / 25, pj = it - pi * 25;
        const int i0 = 2 * pi, j0 = 2 * pj;
        const int i1 = (i0 + 1 < NTOK) ? i0 + 1 : i0;
        const int j1 = (j0 + 1 < NTOK) ? j0 + 1 : j0;
        float s00 = 0.f, s01 = 0.f, s10 = 0.f, s11 = 0.f;
#pragma unroll
        for (int d = 0; d < HD; d++) {
            const float qa = qs[i0][d], qb = qs[i1][d];
            const float ka = ks[j0][d], kb = ks[j1][d];
            s00 = fmaf(qa, ka, s00); s01 = fmaf(qa, kb, s01);
            s10 = fmaf(qb, ka, s10); s11 = fmaf(qb, kb, s11);
        }
        sc[i0][j0] = s00 + bias_table[rel_idx[i0 * NTOK + j0] * NH + hh];
        if (j0 + 1 < NTOK)
            sc[i0][j1] = s01 + bias_table[rel_idx[i0 * NTOK + j1] * NH + hh];
        if (i0 + 1 < NTOK) {
            sc[i1][j0] = s10 + bias_table[rel_idx[i1 * NTOK + j0] * NH + hh];
            if (j0 + 1 < NTOK)
                sc[i1][j1] = s11 + bias_table[rel_idx[i1 * NTOK + j1] * NH + hh];
        }
    }
    __syncthreads();

    if (tid < NTOK) {
        float m = -1e30f;
#pragma unroll 7
        for (int j = 0; j < NTOK; j++) m = fmaxf(m, sc[tid][j]);
        float sum = 0.f;
#pragma unroll 7
        for (int j = 0; j < NTOK; j++) {
            const float e = __expf(sc[tid][j] - m);
            sc[tid][j] = e;
            sum += e;
        }
        const float inv = 1.f / sum;
#pragma unroll 7
        for (int j = 0; j < NTOK; j++) sc[tid][j] *= inv;
    }
    __syncthreads();

    if (tid < 200) {
        const int pi = tid >> 3, pd = tid & 7;
        const int i0 = 2 * pi, d0 = 4 * pd;
        const int i1 = (i0 + 1 < NTOK) ? i0 + 1 : i0;
        float a0 = 0.f, a1 = 0.f, a2 = 0.f, a3 = 0.f;
        float b0 = 0.f, b1 = 0.f, b2 = 0.f, b3 = 0.f;
#pragma unroll
        for (int j = 0; j < NTOK; j++) {
            const float pa = sc[i0][j], pb = sc[i1][j];
            const float v0 = vs[j][d0], v1 = vs[j][d0 + 1];
            const float v2 = vs[j][d0 + 2], v3 = vs[j][d0 + 3];
            a0 = fmaf(pa, v0, a0); a1 = fmaf(pa, v1, a1);
            a2 = fmaf(pa, v2, a2); a3 = fmaf(pa, v3, a3);
            b0 = fmaf(pb, v0, b0); b1 = fmaf(pb, v1, b1);
            b2 = fmaf(pb, v2, b2); b3 = fmaf(pb, v3, b3);
        }
        {
            __half h0, h1, h2, h3, l0, l1, l2, l3;
            split1(a0, h0, l0); split1(a1, h1, l1);
            split1(a2, h2, l2); split1(a3, h3, l3);
            uint32_t* p = (uint32_t*)(outs + (rowbase + i0) * KEFF + hh * HD + d0);
            p[0] = pack_h(h0, h1);   p[1] = pack_h(h2, h3);
            p[256] = pack_h(l0, l1); p[257] = pack_h(l2, l3);
        }
        if (i0 + 1 < NTOK) {
            __half h0, h1, h2, h3, l0, l1, l2, l3;
            split1(b0, h0, l0); split1(b1, h1, l1);
            split1(b2, h2, l2); split1(b3, h3, l3);
            uint32_t* p = (uint32_t*)(outs + (rowbase + i1) * KEFF + hh * HD + d0);
            p[0] = pack_h(h0, h1);   p[1] = pack_h(h2, h3);
            p[256] = pack_h(l0, l1); p[257] = pack_h(l2, l3);
        }
    }
}

// =====================================================================
// launch
// =====================================================================
static inline void launch_split(const float* src, __half* dst,
                                size_t nelem, int mode) {
    const int n4 = (int)(nelem / 4);
    split2_kernel<<<(n4 + 255) / 256, 256>>>(src, dst, n4, mode);
}

extern "C" void kernel_launch(void* const* d_in, const int* in_sizes, int n_in,
                              void* d_out, int out_size)
{
    const float* x          = (const float*)d_in[0];
    const float* w_qkv      = (const float*)d_in[1];
    const float* b_qkv      = (const float*)d_in[2];
    const float* w_gamma    = (const float*)d_in[3];
    const float* b_gamma    = (const float*)d_in[4];
    const float* w_proj     = (const float*)d_in[5];
    const float* b_proj     = (const float*)d_in[6];
    const float* bias_table = (const float*)d_in[7];
    const int*   rel_idx    = (const int*)d_in[8];
    float* out = (float*)d_out;

    float* qkv_buf;
    __half *A3, *A3b, *B3;
    cudaGetSymbolAddress((void**)&qkv_buf, g_qkv);
    cudaGetSymbolAddress((void**)&A3,  g_A3);
    cudaGetSymbolAddress((void**)&A3b, g_A3b);
    cudaGetSymbolAddress((void**)&B3,  g_B3);

    cudaFuncSetAttribute(gemm_fp16x2, cudaFuncAttributeMaxDynamicSharedMemorySize, GEMM_SMEM);

    // 1) qkv = x @ w_qkv^T + b_qkv   [100352, 1536] fp32
    launch_split(x, A3, (size_t)M_TOT * CDIM, 0);
    launch_split(w_qkv, B3, (size_t)3 * CDIM * CDIM, 1);
    {
        dim3 grid(3 * CDIM / 128, M_TOT / 128);
        gemm_fp16x2<<<grid, 256, GEMM_SMEM>>>(A3, B3, b_qkv, qkv_buf, nullptr, 3 * CDIM, 0);
    }
    // 2) attention -> A3b (fp16 hi|lo layout)
    {
        dim3 grid(BATCH, NH);
        attn_kernel<<<grid, 256>>>(qkv_buf, bias_table, rel_idx, A3b);
    }
    // 3) gamma -> A3 (fp16 hi|lo layout)
    launch_split(w_gamma, B3, (size_t)CDIM * CDIM, 1);
    {
        dim3 grid(CDIM / 128, M_TOT / 128);
        gemm_fp16x2<<<grid, 256, GEMM_SMEM>>>(A3b, B3, b_gamma, nullptr, A3, CDIM, 1);
    }
    // 4) out = gamma_out @ w_proj^T + b_proj -> d_out fp32
    launch_split(w_proj, B3, (size_t)CDIM * CDIM, 1);
    {
        dim3 grid(CDIM / 128, M_TOT / 128);
        gemm_fp16x2<<<grid, 256, GEMM_SMEM>>>(A3, B3, b_proj, out, nullptr, CDIM, 0);
    }
}

// round 11
// speedup vs baseline: 1.7336x; 1.3174x over previous
#include <cuda_runtime.h>
#include <cuda_fp16.h>
#include <cstdint>
#include <cstddef>

#define WIN 7
#define NTOK 49
#define NH 16
#define HD 32
#define CDIM 512
#define BATCH 2048
#define M_TOT (BATCH * NTOK)   // 100352 = 784 * 128
#define KEFF 512               // plain fp16, K = C

// ---------------- scratch (static device globals; no allocations) ----------------
__device__ __half g_x16  [(size_t)M_TOT * CDIM];       // 103 MB
__device__ __half g_qkv16[(size_t)M_TOT * 3 * CDIM];   // 308 MB
__device__ __half g_att16[(size_t)M_TOT * CDIM];       // 103 MB
__device__ __half g_g16  [(size_t)M_TOT * CDIM];       // 103 MB
__device__ __half g_W16  [(size_t)3 * CDIM * CDIM];    // 1.6 MB

// =====================================================================
// helpers
// =====================================================================
__device__ __forceinline__ uint32_t smem_u32(const void* p) {
    uint32_t a;
    asm("{ .reg .u64 t; cvta.to.shared.u64 t, %1; cvt.u32.u64 %0, t; }" : "=r"(a) : "l"(p));
    return a;
}
__device__ __forceinline__ void cp16(uint32_t s, const void* g) {
    asm volatile("cp.async.cg.shared.global [%0], [%1], 16;" :: "r"(s), "l"(g));
}
__device__ __forceinline__ uint32_t pack_h(__half a, __half b) {
    return ((uint32_t)__half_as_ushort(b) << 16) | __half_as_ushort(a);
}

// =====================================================================
// fp32 -> fp16 convert (vectorized)
// =====================================================================
__global__ void cvt_fp16_kernel(const float* __restrict__ src,
                                __half* __restrict__ dst, int n4)
{
    int i = blockIdx.x * blockDim.x + threadIdx.x;
    if (i >= n4) return;
    float4 v = ((const float4*)src)[i];
    uint32_t* p = (uint32_t*)(dst + (size_t)i * 4);
    p[0] = pack_h(__float2half_rn(v.x), __float2half_rn(v.y));
    p[1] = pack_h(__float2half_rn(v.z), __float2half_rn(v.w));
}

// =====================================================================
// FP16 GEMM via mma.sync:  C[M,N] = A[M,512] * B[N,512]^T + bias[N]
// CTA tile 128x128, BK=64, 3-stage cp.async, 256 threads (8 warps 2x4),
// warp tile 64x32.  (R7 geometry, 2 CTA/SM.)
// out_mode=0: fp32 Cf[M,N].  out_mode=1: fp16 Ch[M,N].
// =====================================================================
#define BKB 64
#define NKIT (KEFF / BKB)            // 8
#define STAGE_A (128 * BKB * 2)      // 16384
#define STAGE_BYTES (2 * STAGE_A)    // 32768 (A then B)
#define GEMM_SMEM (3 * STAGE_BYTES)  // 98304

__global__ void __launch_bounds__(256)
gemm_fp16(const __half* __restrict__ A,
          const __half* __restrict__ B,
          const float* __restrict__ bias,
          float* __restrict__ Cf,
          __half* __restrict__ Ch,
          int N, int out_mode)
{
    extern __shared__ char smem[];
    const uint32_t sb = smem_u32(smem);
    const int tid  = threadIdx.x;
    const int lane = tid & 31;
    const int wid  = tid >> 5;
    const int wm   = wid >> 2;
    const int wn   = wid & 3;

    const __half* Ag = A + (size_t)blockIdx.y * 128 * KEFF;
    const __half* Bg = B + (size_t)blockIdx.x * 128 * KEFF;

    const int lr = tid >> 3;
    const int lc = tid & 7;

    auto load_stage = [&](int kt, int slot) {
        const uint32_t base = sb + (uint32_t)slot * STAGE_BYTES;
        const int kof = kt * BKB;
#pragma unroll
        for (int i = 0; i < 4; i++) {
            const int r = lr + i * 32;
            const uint32_t so = (uint32_t)r * 128 + (uint32_t)((lc ^ (r & 7)) << 4);
            cp16(base + so,           Ag + (size_t)r * KEFF + kof + lc * 8);
            cp16(base + STAGE_A + so, Bg + (size_t)r * KEFF + kof + lc * 8);
        }
    };

    float acc[4][4][4];
#pragma unroll
    for (int a = 0; a < 4; a++)
#pragma unroll
        for (int b = 0; b < 4; b++)
#pragma unroll
            for (int c = 0; c < 4; c++) acc[a][b][c] = 0.f;

    load_stage(0, 0); asm volatile("cp.async.commit_group;" ::: "memory");
    load_stage(1, 1); asm volatile("cp.async.commit_group;" ::: "memory");

    const int rA0 = wm * 64 + (lane & 15);
    const int cAh = lane >> 4;
    const int rB0 = wn * 32 + (lane & 7);
    const int cBh = (lane >> 3) & 1;

    for (int kt = 0; kt < NKIT; kt++) {
        asm volatile("cp.async.wait_group 1;" ::: "memory");
        __syncthreads();
        if (kt + 2 < NKIT) load_stage(kt + 2, (kt + 2) % 3);
        asm volatile("cp.async.commit_group;" ::: "memory");

        const uint32_t base = sb + (uint32_t)(kt % 3) * STAGE_BYTES;
#pragma unroll
        for (int kk = 0; kk < 4; kk++) {
            uint32_t afr[4][4];
#pragma unroll
            for (int im = 0; im < 4; im++) {
                const int r = rA0 + im * 16;
                const uint32_t addr = base + (uint32_t)r * 128 +
                    (uint32_t)(((2 * kk + cAh) ^ (r & 7)) << 4);
                asm volatile("ldmatrix.sync.aligned.m8n8.x4.shared.b16 {%0,%1,%2,%3}, [%4];"
                    : "=r"(afr[im][0]), "=r"(afr[im][1]), "=r"(afr[im][2]), "=r"(afr[im][3])
                    : "r"(addr));
            }
            uint32_t bfr[4][2];
#pragma unroll
            for (int in = 0; in < 4; in++) {
                const int r = rB0 + in * 8;
                const uint32_t addr = base + STAGE_A + (uint32_t)r * 128 +
                    (uint32_t)(((2 * kk + cBh) ^ (r & 7)) << 4);
                asm volatile("ldmatrix.sync.aligned.m8n8.x2.shared.b16 {%0,%1}, [%2];"
                    : "=r"(bfr[in][0]), "=r"(bfr[in][1]) : "r"(addr));
            }
#pragma unroll
            for (int im = 0; im < 4; im++)
#pragma unroll
                for (int in = 0; in < 4; in++) {
                    asm volatile(
                        "mma.sync.aligned.m16n8k16.row.col.f32.f16.f16.f32 "
                        "{%0,%1,%2,%3}, {%4,%5,%6,%7}, {%8,%9}, {%0,%1,%2,%3};"
                        : "+f"(acc[im][in][0]), "+f"(acc[im][in][1]),
                          "+f"(acc[im][in][2]), "+f"(acc[im][in][3])
                        : "r"(afr[im][0]), "r"(afr[im][1]), "r"(afr[im][2]), "r"(afr[im][3]),
                          "r"(bfr[in][0]), "r"(bfr[in][1]));
                }
        }
    }

    // ---- epilogue ----
    const int mBase = blockIdx.y * 128 + wm * 64;
    const int nBase = blockIdx.x * 128 + wn * 32;
    const int rr = lane >> 2;
    const int cc = (lane & 3) * 2;

    if (!out_mode) {
#pragma unroll
        for (int im = 0; im < 4; im++)
#pragma unroll
            for (int in = 0; in < 4; in++) {
                const int row = mBase + im * 16 + rr;
                const int col = nBase + in * 8 + cc;
                const float bx = bias[col], by = bias[col + 1];
                *(float2*)(Cf + (size_t)row * N + col) =
                    make_float2(acc[im][in][0] + bx, acc[im][in][1] + by);
                *(float2*)(Cf + (size_t)(row + 8) * N + col) =
                    make_float2(acc[im][in][2] + bx, acc[im][in][3] + by);
            }
    } else {
#pragma unroll
        for (int im = 0; im < 4; im++)
#pragma unroll
            for (int in = 0; in < 4; in++) {
                const int row = mBase + im * 16 + rr;
                const int col = nBase + in * 8 + cc;
                const float bx = bias[col], by = bias[col + 1];
                *(uint32_t*)(Ch + (size_t)row * N + col) =
                    pack_h(__float2half_rn(acc[im][in][0] + bx),
                           __float2half_rn(acc[im][in][1] + by));
                *(uint32_t*)(Ch + (size_t)(row + 8) * N + col) =
                    pack_h(__float2half_rn(acc[im][in][2] + bx),
                           __float2half_rn(acc[im][in][3] + by));
            }
    }
}

// =====================================================================
// fused windowed attention (register-blocked), fp16 in / fp16 out
// =====================================================================
__global__ __launch_bounds__(256)
void attn_kernel(const __half* __restrict__ qkv,      // [M_TOT, 1536]
                 const float* __restrict__ bias_table,
                 const int*   __restrict__ rel_idx,
                 __half* __restrict__ outs)            // [M_TOT, 512]
{
    const int b  = blockIdx.x;
    const int hh = blockIdx.y;
    const int tid = threadIdx.x;

    __shared__ float qs[NTOK][HD + 1];
    __shared__ float ks[NTOK][HD + 1];
    __shared__ float vs[NTOK][HD + 1];
    __shared__ float sc[NTOK][NTOK + 1];

    const size_t rowbase = (size_t)b * NTOK;

    for (int idx = tid; idx < NTOK * HD; idx += 256) {
        const int i = idx >> 5, d = idx & 31;
        const size_t base = (rowbase + i) * (3 * CDIM) + hh * HD + d;
        qs[i][d] = __half2float(qkv[base]) * 0.25f;
        ks[i][d] = __half2float(qkv[base + CDIM]);
        vs[i][d] = __half2float(qkv[base + 2 * CDIM]);
    }
    __syncthreads();

    for (int it = tid; it < 625; it += 256) {
        const int pi = it / 25, pj = it - pi * 25;
        const int i0 = 2 * pi, j0 = 2 * pj;
        const int i1 = (i0 + 1 < NTOK) ? i0 + 1 : i0;
        const int j1 = (j0 + 1 < NTOK) ? j0 + 1 : j0;
        float s00 = 0.f, s01 = 0.f, s10 = 0.f, s11 = 0.f;
#pragma unroll
        for (int d = 0; d < HD; d++) {
            const float qa = qs[i0][d], qb = qs[i1][d];
            const float ka = ks[j0][d], kb = ks[j1][d];
            s00 = fmaf(qa, ka, s00); s01 = fmaf(qa, kb, s01);
            s10 = fmaf(qb, ka, s10); s11 = fmaf(qb, kb, s11);
        }
        sc[i0][j0] = s00 + bias_table[rel_idx[i0 * NTOK + j0] * NH + hh];
        if (j0 + 1 < NTOK)
            sc[i0][j1] = s01 + bias_table[rel_idx[i0 * NTOK + j1] * NH + hh];
        if (i0 + 1 < NTOK) {
            sc[i1][j0] = s10 + bias_table[rel_idx[i1 * NTOK + j0] * NH + hh];
            if (j0 + 1 < NTOK)
                sc[i1][j1] = s11 + bias_table[rel_idx[i1 * NTOK + j1] * NH + hh];
        }
    }
    __syncthreads();

    if (tid < NTOK) {
        float m = -1e30f;
#pragma unroll 7
        for (int j = 0; j < NTOK; j++) m = fmaxf(m, sc[tid][j]);
        float sum = 0.f;
#pragma unroll 7
        for (int j = 0; j < NTOK; j++) {
            const float e = __expf(sc[tid][j] - m);
            sc[tid][j] = e;
            sum += e;
        }
        const float inv = 1.f / sum;
#pragma unroll 7
        for (int j = 0; j < NTOK; j++) sc[tid][j] *= inv;
    }
    __syncthreads();

    if (tid < 200) {
        const int pi = tid >> 3, pd = tid & 7;
        const int i0 = 2 * pi, d0 = 4 * pd;
        const int i1 = (i0 + 1 < NTOK) ? i0 + 1 : i0;
        float a0 = 0.f, a1 = 0.f, a2 = 0.f, a3 = 0.f;
        float b0 = 0.f, b1 = 0.f, b2 = 0.f, b3 = 0.f;
#pragma unroll
        for (int j = 0; j < NTOK; j++) {
            const float pa = sc[i0][j], pb = sc[i1][j];
            const float v0 = vs[j][d0], v1 = vs[j][d0 + 1];
            const float v2 = vs[j][d0 + 2], v3 = vs[j][d0 + 3];
            a0 = fmaf(pa, v0, a0); a1 = fmaf(pa, v1, a1);
            a2 = fmaf(pa, v2, a2); a3 = fmaf(pa, v3, a3);
            b0 = fmaf(pb, v0, b0); b1 = fmaf(pb, v1, b1);
            b2 = fmaf(pb, v2, b2); b3 = fmaf(pb, v3, b3);
        }
        {
            uint32_t* p = (uint32_t*)(outs + (rowbase + i0) * CDIM + hh * HD + d0);
            p[0] = pack_h(__float2half_rn(a0), __float2half_rn(a1));
            p[1] = pack_h(__float2half_rn(a2), __float2half_rn(a3));
        }
        if (i0 + 1 < NTOK) {
            uint32_t* p = (uint32_t*)(outs + (rowbase + i1) * CDIM + hh * HD + d0);
            p[0] = pack_h(__float2half_rn(b0), __float2half_rn(b1));
            p[1] = pack_h(__float2half_rn(b2), __float2half_rn(b3));
        }
    }
}

// =====================================================================
// launch
// =====================================================================
static inline void launch_cvt(const float* src, __half* dst, size_t nelem) {
    const int n4 = (int)(nelem / 4);
    cvt_fp16_kernel<<<(n4 + 255) / 256, 256>>>(src, dst, n4);
}

extern "C" void kernel_launch(void* const* d_in, const int* in_sizes, int n_in,
                              void* d_out, int out_size)
{
    const float* x          = (const float*)d_in[0];
    const float* w_qkv      = (const float*)d_in[1];
    const float* b_qkv      = (const float*)d_in[2];
    const float* w_gamma    = (const float*)d_in[3];
    const float* b_gamma    = (const float*)d_in[4];
    const float* w_proj     = (const float*)d_in[5];
    const float* b_proj     = (const float*)d_in[6];
    const float* bias_table = (const float*)d_in[7];
    const int*   rel_idx    = (const int*)d_in[8];
    float* out = (float*)d_out;

    __half *X16, *QKV16, *ATT16, *G16, *W16;
    cudaGetSymbolAddress((void**)&X16,   g_x16);
    cudaGetSymbolAddress((void**)&QKV16, g_qkv16);
    cudaGetSymbolAddress((void**)&ATT16, g_att16);
    cudaGetSymbolAddress((void**)&G16,   g_g16);
    cudaGetSymbolAddress((void**)&W16,   g_W16);

    cudaFuncSetAttribute(gemm_fp16, cudaFuncAttributeMaxDynamicSharedMemorySize, GEMM_SMEM);

    // 1) qkv = x @ w_qkv^T + b_qkv   -> fp16 [100352, 1536]
    launch_cvt(x, X16, (size_t)M_TOT * CDIM);
    launch_cvt(w_qkv, W16, (size_t)3 * CDIM * CDIM);
    {
        dim3 grid(3 * CDIM / 128, M_TOT / 128);
        gemm_fp16<<<grid, 256, GEMM_SMEM>>>(X16, W16, b_qkv, nullptr, QKV16, 3 * CDIM, 1);
    }
    // 2) attention -> ATT16 fp16 [100352, 512]
    {
        dim3 grid(BATCH, NH);
        attn_kernel<<<grid, 256>>>(QKV16, bias_table, rel_idx, ATT16);
    }
    // 3) gamma -> G16 fp16
    launch_cvt(w_gamma, W16, (size_t)CDIM * CDIM);
    {
        dim3 grid(CDIM / 128, M_TOT / 128);
        gemm_fp16<<<grid, 256, GEMM_SMEM>>>(ATT16, W16, b_gamma, nullptr, G16, CDIM, 1);
    }
    // 4) out = g @ w_proj^T + b_proj -> fp32 d_out
    launch_cvt(w_proj, W16, (size_t)CDIM * CDIM);
    {
        dim3 grid(CDIM / 128, M_TOT / 128);
        gemm_fp16<<<grid, 256, GEMM_SMEM>>>(G16, W16, b_proj, out, nullptr, CDIM, 0);
    }
}

// round 12
// speedup vs baseline: 2.1107x; 1.2175x over previous
#include <cuda_runtime.h>
#include <cuda_fp16.h>
#include <cstdint>
#include <cstddef>

#define WIN 7
#define NTOK 49
#define NH 16
#define HD 32
#define CDIM 512
#define BATCH 2048
#define M_TOT (BATCH * NTOK)   // 100352 = 784 * 128
#define KEFF 512

// ---------------- scratch (static device globals; no allocations) ----------------
__device__ __half g_x16  [(size_t)M_TOT * CDIM];       // 103 MB
__device__ __half g_qkv16[(size_t)M_TOT * 3 * CDIM];   // 308 MB
__device__ __half g_att16[(size_t)M_TOT * CDIM];       // 103 MB
__device__ __half g_g16  [(size_t)M_TOT * CDIM];       // 103 MB
__device__ __half g_W16  [(size_t)3 * CDIM * CDIM];    // 1.6 MB
__device__ float  g_biasf[(size_t)NH * 64 * 56];       // 229 KB (masked bias table)

// =====================================================================
// helpers
// =====================================================================
__device__ __forceinline__ uint32_t smem_u32(const void* p) {
    uint32_t a;
    asm("{ .reg .u64 t; cvta.to.shared.u64 t, %1; cvt.u32.u64 %0, t; }" : "=r"(a) : "l"(p));
    return a;
}
__device__ __forceinline__ void cp16(uint32_t s, const void* g) {
    asm volatile("cp.async.cg.shared.global [%0], [%1], 16;" :: "r"(s), "l"(g));
}
__device__ __forceinline__ uint32_t pack_h(__half a, __half b) {
    return ((uint32_t)__half_as_ushort(b) << 16) | __half_as_ushort(a);
}
__device__ __forceinline__ uint32_t f2h2(float a, float b) {
    __half2 h = __floats2half2_rn(a, b);
    return *(uint32_t*)&h;
}
#define MMA16816(d, a0, a1, a2, a3, b0, b1)                                   \
    asm volatile(                                                             \
        "mma.sync.aligned.m16n8k16.row.col.f32.f16.f16.f32 "                  \
        "{%0,%1,%2,%3}, {%4,%5,%6,%7}, {%8,%9}, {%0,%1,%2,%3};"               \
        : "+f"((d)[0]), "+f"((d)[1]), "+f"((d)[2]), "+f"((d)[3])              \
        : "r"(a0), "r"(a1), "r"(a2), "r"(a3), "r"(b0), "r"(b1))

// =====================================================================
// fp32 -> fp16 convert (vectorized)
// =====================================================================
__global__ void cvt_fp16_kernel(const float* __restrict__ src,
                                __half* __restrict__ dst, int n4)
{
    int i = blockIdx.x * blockDim.x + threadIdx.x;
    if (i >= n4) return;
    float4 v = ((const float4*)src)[i];
    uint32_t* p = (uint32_t*)(dst + (size_t)i * 4);
    p[0] = pack_h(__float2half_rn(v.x), __float2half_rn(v.y));
    p[1] = pack_h(__float2half_rn(v.z), __float2half_rn(v.w));
}

// =====================================================================
// precompute masked bias table: bf[h][i(64)][j(56)]
//   j >= 49 -> -1e30 (mask), i >= 49 -> 0, else gathered rel-pos bias
// =====================================================================
__global__ void bias_pre_kernel(const float* __restrict__ bias_table,
                                const int* __restrict__ rel_idx,
                                float* __restrict__ bf)
{
    int idx = blockIdx.x * 256 + threadIdx.x;
    if (idx >= NH * 64 * 56) return;
    const int j = idx % 56;
    const int i = (idx / 56) % 64;
    const int h = idx / (56 * 64);
    float v;
    if (j >= NTOK)      v = -1e30f;
    else if (i >= NTOK) v = 0.f;
    else                v = bias_table[rel_idx[i * NTOK + j] * NH + h];
    bf[idx] = v;
}

// =====================================================================
// FP16 GEMM via mma.sync (R11 geometry, unchanged)
// =====================================================================
#define BKB 64
#define NKIT (KEFF / BKB)            // 8
#define STAGE_A (128 * BKB * 2)      // 16384
#define STAGE_BYTES (2 * STAGE_A)    // 32768
#define GEMM_SMEM (3 * STAGE_BYTES)  // 98304

__global__ void __launch_bounds__(256)
gemm_fp16(const __half* __restrict__ A,
          const __half* __restrict__ B,
          const float* __restrict__ bias,
          float* __restrict__ Cf,
          __half* __restrict__ Ch,
          int N, int out_mode)
{
    extern __shared__ char smem[];
    const uint32_t sb = smem_u32(smem);
    const int tid  = threadIdx.x;
    const int lane = tid & 31;
    const int wid  = tid >> 5;
    const int wm   = wid >> 2;
    const int wn   = wid & 3;

    const __half* Ag = A + (size_t)blockIdx.y * 128 * KEFF;
    const __half* Bg = B + (size_t)blockIdx.x * 128 * KEFF;

    const int lr = tid >> 3;
    const int lc = tid & 7;

    auto load_stage = [&](int kt, int slot) {
        const uint32_t base = sb + (uint32_t)slot * STAGE_BYTES;
        const int kof = kt * BKB;
#pragma unroll
        for (int i = 0; i < 4; i++) {
            const int r = lr + i * 32;
            const uint32_t so = (uint32_t)r * 128 + (uint32_t)((lc ^ (r & 7)) << 4);
            cp16(base + so,           Ag + (size_t)r * KEFF + kof + lc * 8);
            cp16(base + STAGE_A + so, Bg + (size_t)r * KEFF + kof + lc * 8);
        }
    };

    float acc[4][4][4];
#pragma unroll
    for (int a = 0; a < 4; a++)
#pragma unroll
        for (int b = 0; b < 4; b++)
#pragma unroll
            for (int c = 0; c < 4; c++) acc[a][b][c] = 0.f;

    load_stage(0, 0); asm volatile("cp.async.commit_group;" ::: "memory");
    load_stage(1, 1); asm volatile("cp.async.commit_group;" ::: "memory");

    const int rA0 = wm * 64 + (lane & 15);
    const int cAh = lane >> 4;
    const int rB0 = wn * 32 + (lane & 7);
    const int cBh = (lane >> 3) & 1;

    for (int kt = 0; kt < NKIT; kt++) {
        asm volatile("cp.async.wait_group 1;" ::: "memory");
        __syncthreads();
        if (kt + 2 < NKIT) load_stage(kt + 2, (kt + 2) % 3);
        asm volatile("cp.async.commit_group;" ::: "memory");

        const uint32_t base = sb + (uint32_t)(kt % 3) * STAGE_BYTES;
#pragma unroll
        for (int kk = 0; kk < 4; kk++) {
            uint32_t afr[4][4];
#pragma unroll
            for (int im = 0; im < 4; im++) {
                const int r = rA0 + im * 16;
                const uint32_t addr = base + (uint32_t)r * 128 +
                    (uint32_t)(((2 * kk + cAh) ^ (r & 7)) << 4);
                asm volatile("ldmatrix.sync.aligned.m8n8.x4.shared.b16 {%0,%1,%2,%3}, [%4];"
                    : "=r"(afr[im][0]), "=r"(afr[im][1]), "=r"(afr[im][2]), "=r"(afr[im][3])
                    : "r"(addr));
            }
            uint32_t bfr[4][2];
#pragma unroll
            for (int in = 0; in < 4; in++) {
                const int r = rB0 + in * 8;
                const uint32_t addr = base + STAGE_A + (uint32_t)r * 128 +
                    (uint32_t)(((2 * kk + cBh) ^ (r & 7)) << 4);
                asm volatile("ldmatrix.sync.aligned.m8n8.x2.shared.b16 {%0,%1}, [%2];"
                    : "=r"(bfr[in][0]), "=r"(bfr[in][1]) : "r"(addr));
            }
#pragma unroll
            for (int im = 0; im < 4; im++)
#pragma unroll
                for (int in = 0; in < 4; in++)
                    MMA16816(acc[im][in], afr[im][0], afr[im][1], afr[im][2], afr[im][3],
                             bfr[in][0], bfr[in][1]);
        }
    }

    const int mBase = blockIdx.y * 128 + wm * 64;
    const int nBase = blockIdx.x * 128 + wn * 32;
    const int rr = lane >> 2;
    const int cc = (lane & 3) * 2;

    if (!out_mode) {
#pragma unroll
        for (int im = 0; im < 4; im++)
#pragma unroll
            for (int in = 0; in < 4; in++) {
                const int row = mBase + im * 16 + rr;
                const int col = nBase + in * 8 + cc;
                const float bx = bias[col], by = bias[col + 1];
                *(float2*)(Cf + (size_t)row * N + col) =
                    make_float2(acc[im][in][0] + bx, acc[im][in][1] + by);
                *(float2*)(Cf + (size_t)(row + 8) * N + col) =
                    make_float2(acc[im][in][2] + bx, acc[im][in][3] + by);
            }
    } else {
#pragma unroll
        for (int im = 0; im < 4; im++)
#pragma unroll
            for (int in = 0; in < 4; in++) {
                const int row = mBase + im * 16 + rr;
                const int col = nBase + in * 8 + cc;
                const float bx = bias[col], by = bias[col + 1];
                *(uint32_t*)(Ch + (size_t)row * N + col) =
                    pack_h(__float2half_rn(acc[im][in][0] + bx),
                           __float2half_rn(acc[im][in][1] + by));
                *(uint32_t*)(Ch + (size_t)(row + 8) * N + col) =
                    pack_h(__float2half_rn(acc[im][in][2] + bx),
                           __float2half_rn(acc[im][in][3] + by));
            }
    }
}

// =====================================================================
// tensor-core windowed attention: 256 threads, 2 heads/CTA (4 warps/head)
// S = (Q*0.25)K^T + bias (masked), softmax, O = P V.  All frags via LDS.32.
// =====================================================================
// smem (halfwords): Q[2][64][40] @0, K[2][64][40] @5120, Vt[2][32][72] @10240
#define QOFF  0
#define KOFF  5120
#define VTOFF 10240
#define ATT_HALVES 14848   // 29696 bytes

__global__ void __launch_bounds__(256)
attn_mma_kernel(const __half* __restrict__ qkv,     // [M_TOT, 1536]
                const float* __restrict__ bf,       // [16][64][56]
                __half* __restrict__ outs)          // [M_TOT, 512]
{
    __shared__ __align__(16) __half sm[ATT_HALVES];

    const int b  = blockIdx.x;
    const int h0 = blockIdx.y * 2;
    const int tid = threadIdx.x;
    const uint32_t sb = smem_u32(sm);
    const size_t rowbase = (size_t)b * NTOK;

    // ---- zero smem (padding must be 0) ----
    {
        uint4 z = make_uint4(0, 0, 0, 0);
        for (int i = tid; i < ATT_HALVES / 8; i += 256)
            ((uint4*)sm)[i] = z;
    }
    __syncthreads();

    // ---- load Q,K via cp.async (rows < 49); V transposed via LDG+STS ----
    for (int it = tid; it < 784; it += 256) {            // 2 mats * 2 heads * 49 rows * 4 chunks
        const int c   = it & 3;
        const int r3  = it >> 2;
        const int row = r3 % 49;
        const int mh  = r3 / 49;          // 0..3
        const int head = mh & 1;
        const int mat  = mh >> 1;          // 0=Q, 1=K
        const __half* g = qkv + (rowbase + row) * (3 * CDIM) + mat * CDIM + (h0 + head) * HD + c * 8;
        const uint32_t dst = sb + (uint32_t)(mat * KOFF + head * 2560 + row * 40 + c * 8) * 2;
        cp16(dst, g);
    }
    for (int it = tid; it < 1568; it += 256) {           // 2 heads * 49 rows * 16 u32
        const int c   = it & 15;          // d pair
        const int r2  = it >> 4;
        const int row = r2 % 49;
        const int head = r2 / 49;
        const uint32_t v = *(const uint32_t*)(qkv + (rowbase + row) * (3 * CDIM) + 2 * CDIM + (h0 + head) * HD + 2 * c);
        __half* base = sm + VTOFF + head * 2304;
        base[(2 * c) * 72 + row]     = __ushort_as_half((unsigned short)(v & 0xFFFF));
        base[(2 * c + 1) * 72 + row] = __ushort_as_half((unsigned short)(v >> 16));
    }
    asm volatile("cp.async.commit_group;" ::: "memory");
    asm volatile("cp.async.wait_group 0;" ::: "memory");
    __syncthreads();

    // ---- per-warp compute ----
    const int lane = tid & 31;
    const int wid  = tid >> 5;
    const int head = wid >> 2;      // 0..1
    const int w    = wid & 3;       // M-tile
    const int g    = lane >> 2;     // group id (row/col within 8)
    const int t4   = lane & 3;

    const __half* Q  = sm + QOFF  + head * 2560;
    const __half* K  = sm + KOFF  + head * 2560;
    const __half* Vt = sm + VTOFF + head * 2304;

    // S accumulators: 7 n-tiles
    float sc[7][4];
#pragma unroll
    for (int n = 0; n < 7; n++)
#pragma unroll
        for (int c = 0; c < 4; c++) sc[n][c] = 0.f;

#pragma unroll
    for (int kh = 0; kh < 2; kh++) {
        const int kc = 16 * kh + 2 * t4;
        const uint32_t a0 = *(const uint32_t*)&Q[(16 * w + g) * 40 + kc];
        const uint32_t a1 = *(const uint32_t*)&Q[(16 * w + g + 8) * 40 + kc];
        const uint32_t a2 = *(const uint32_t*)&Q[(16 * w + g) * 40 + kc + 8];
        const uint32_t a3 = *(const uint32_t*)&Q[(16 * w + g + 8) * 40 + kc + 8];
#pragma unroll
        for (int nt = 0; nt < 7; nt++) {
            const uint32_t b0 = *(const uint32_t*)&K[(8 * nt + g) * 40 + kc];
            const uint32_t b1 = *(const uint32_t*)&K[(8 * nt + g) * 40 + kc + 8];
            MMA16816(sc[nt], a0, a1, a2, a3, b0, b1);
        }
    }

    // ---- scale + bias + softmax (deferred normalization) ----
    const float* bfr0 = bf + ((size_t)(h0 + head) * 64 + 16 * w + g) * 56;
    const float* bfr1 = bfr0 + 8 * 56;
    float m0 = -1e30f, m1 = -1e30f;
#pragma unroll
    for (int nt = 0; nt < 7; nt++) {
        const float2 bb0 = *(const float2*)&bfr0[8 * nt + 2 * t4];
        const float2 bb1 = *(const float2*)&bfr1[8 * nt + 2 * t4];
        sc[nt][0] = fmaf(sc[nt][0], 0.25f, bb0.x);
        sc[nt][1] = fmaf(sc[nt][1], 0.25f, bb0.y);
        sc[nt][2] = fmaf(sc[nt][2], 0.25f, bb1.x);
        sc[nt][3] = fmaf(sc[nt][3], 0.25f, bb1.y);
        m0 = fmaxf(m0, fmaxf(sc[nt][0], sc[nt][1]));
        m1 = fmaxf(m1, fmaxf(sc[nt][2], sc[nt][3]));
    }
    m0 = fmaxf(m0, __shfl_xor_sync(0xFFFFFFFF, m0, 1));
    m0 = fmaxf(m0, __shfl_xor_sync(0xFFFFFFFF, m0, 2));
    m1 = fmaxf(m1, __shfl_xor_sync(0xFFFFFFFF, m1, 1));
    m1 = fmaxf(m1, __shfl_xor_sync(0xFFFFFFFF, m1, 2));

    float s0 = 0.f, s1 = 0.f;
#pragma unroll
    for (int nt = 0; nt < 7; nt++) {
        sc[nt][0] = __expf(sc[nt][0] - m0); s0 += sc[nt][0];
        sc[nt][1] = __expf(sc[nt][1] - m0); s0 += sc[nt][1];
        sc[nt][2] = __expf(sc[nt][2] - m1); s1 += sc[nt][2];
        sc[nt][3] = __expf(sc[nt][3] - m1); s1 += sc[nt][3];
    }
    s0 += __shfl_xor_sync(0xFFFFFFFF, s0, 1);
    s0 += __shfl_xor_sync(0xFFFFFFFF, s0, 2);
    s1 += __shfl_xor_sync(0xFFFFFFFF, s1, 1);
    s1 += __shfl_xor_sync(0xFFFFFFFF, s1, 2);
    const float inv0 = 1.f / s0;
    const float inv1 = 1.f / s1;

    // ---- O = P V  (P from C-frags relabelled as A-frags) ----
    float oa[4][4];
#pragma unroll
    for (int n = 0; n < 4; n++)
#pragma unroll
        for (int c = 0; c < 4; c++) oa[n][c] = 0.f;

#pragma unroll
    for (int kt = 0; kt < 4; kt++) {
        const int n0 = 2 * kt, n1 = 2 * kt + 1;
        const uint32_t a0 = f2h2(sc[n0][0], sc[n0][1]);
        const uint32_t a1 = f2h2(sc[n0][2], sc[n0][3]);
        const uint32_t a2 = (n1 < 7) ? f2h2(sc[n1][0], sc[n1][1]) : 0u;
        const uint32_t a3 = (n1 < 7) ? f2h2(sc[n1][2], sc[n1][3]) : 0u;
        const int jc = 16 * kt + 2 * t4;
#pragma unroll
        for (int nt = 0; nt < 4; nt++) {
            const uint32_t b0 = *(const uint32_t*)&Vt[(8 * nt + g) * 72 + jc];
            const uint32_t b1 = *(const uint32_t*)&Vt[(8 * nt + g) * 72 + jc + 8];
            MMA16816(oa[nt], a0, a1, a2, a3, b0, b1);
        }
    }

    // ---- store (normalize here) ----
    const int i0 = 16 * w + g, i1 = i0 + 8;
    const int dc = 2 * t4;
#pragma unroll
    for (int nt = 0; nt < 4; nt++) {
        const int d = 8 * nt + dc;
        if (i0 < NTOK)
            *(uint32_t*)(outs + (rowbase + i0) * CDIM + (h0 + head) * HD + d) =
                f2h2(oa[nt][0] * inv0, oa[nt][1] * inv0);
        if (i1 < NTOK)
            *(uint32_t*)(outs + (rowbase + i1) * CDIM + (h0 + head) * HD + d) =
                f2h2(oa[nt][2] * inv1, oa[nt][3] * inv1);
    }
}

// =====================================================================
// launch
// =====================================================================
static inline void launch_cvt(const float* src, __half* dst, size_t nelem) {
    const int n4 = (int)(nelem / 4);
    cvt_fp16_kernel<<<(n4 + 255) / 256, 256>>>(src, dst, n4);
}

extern "C" void kernel_launch(void* const* d_in, const int* in_sizes, int n_in,
                              void* d_out, int out_size)
{
    const float* x          = (const float*)d_in[0];
    const float* w_qkv      = (const float*)d_in[1];
    const float* b_qkv      = (const float*)d_in[2];
    const float* w_gamma    = (const float*)d_in[3];
    const float* b_gamma    = (const float*)d_in[4];
    const float* w_proj     = (const float*)d_in[5];
    const float* b_proj     = (const float*)d_in[6];
    const float* bias_table = (const float*)d_in[7];
    const int*   rel_idx    = (const int*)d_in[8];
    float* out = (float*)d_out;

    __half *X16, *QKV16, *ATT16, *G16, *W16;
    float* BF;
    cudaGetSymbolAddress((void**)&X16,   g_x16);
    cudaGetSymbolAddress((void**)&QKV16, g_qkv16);
    cudaGetSymbolAddress((void**)&ATT16, g_att16);
    cudaGetSymbolAddress((void**)&G16,   g_g16);
    cudaGetSymbolAddress((void**)&W16,   g_W16);
    cudaGetSymbolAddress((void**)&BF,    g_biasf);

    cudaFuncSetAttribute(gemm_fp16, cudaFuncAttributeMaxDynamicSharedMemorySize, GEMM_SMEM);

    // 0) masked bias table
    bias_pre_kernel<<<(NH * 64 * 56 + 255) / 256, 256>>>(bias_table, rel_idx, BF);

    // 1) qkv = x @ w_qkv^T + b_qkv   -> fp16 [100352, 1536]
    launch_cvt(x, X16, (size_t)M_TOT * CDIM);
    launch_cvt(w_qkv, W16, (size_t)3 * CDIM * CDIM);
    {
        dim3 grid(3 * CDIM / 128, M_TOT / 128);
        gemm_fp16<<<grid, 256, GEMM_SMEM>>>(X16, W16, b_qkv, nullptr, QKV16, 3 * CDIM, 1);
    }
    // 2) tensor-core attention -> ATT16 fp16 [100352, 512]
    {
        dim3 grid(BATCH, NH / 2);
        attn_mma_kernel<<<grid, 256>>>(QKV16, BF, ATT16);
    }
    // 3) gamma -> G16 fp16
    launch_cvt(w_gamma, W16, (size_t)CDIM * CDIM);
    {
        dim3 grid(CDIM / 128, M_TOT / 128);
        gemm_fp16<<<grid, 256, GEMM_SMEM>>>(ATT16, W16, b_gamma, nullptr, G16, CDIM, 1);
    }
    // 4) out = g @ w_proj^T + b_proj -> fp32 d_out
    launch_cvt(w_proj, W16, (size_t)CDIM * CDIM);
    {
        dim3 grid(CDIM / 128, M_TOT / 128);
        gemm_fp16<<<grid, 256, GEMM_SMEM>>>(G16, W16, b_proj, out, nullptr, CDIM, 0);
    }
}

// round 13
// speedup vs baseline: 2.9732x; 1.4086x over previous
#include <cuda_runtime.h>
#include <cuda_fp16.h>
#include <cstdint>
#include <cstddef>

#define WIN 7
#define NTOK 49
#define NH 16
#define HD 32
#define CDIM 512
#define BATCH 2048
#define M_TOT (BATCH * NTOK)   // 100352 = 784 * 128
#define KEFF 512

// ---------------- scratch (static device globals; no allocations) ----------------
__device__ __half g_x16  [(size_t)M_TOT * CDIM];       // 103 MB
__device__ __half g_qkv16[(size_t)M_TOT * 3 * CDIM];   // 308 MB
__device__ __half g_att16[(size_t)M_TOT * CDIM];       // 103 MB
__device__ __half g_g16  [(size_t)M_TOT * CDIM];       // 103 MB
__device__ __half g_W16  [(size_t)3 * CDIM * CDIM];    // 1.6 MB
__device__ float  g_biasf[(size_t)NH * 64 * 56];       // 229 KB (masked bias table)

// =====================================================================
// helpers
// =====================================================================
__device__ __forceinline__ uint32_t smem_u32(const void* p) {
    uint32_t a;
    asm("{ .reg .u64 t; cvta.to.shared.u64 t, %1; cvt.u32.u64 %0, t; }" : "=r"(a) : "l"(p));
    return a;
}
__device__ __forceinline__ void cp16(uint32_t s, const void* g) {
    asm volatile("cp.async.cg.shared.global [%0], [%1], 16;" :: "r"(s), "l"(g));
}
__device__ __forceinline__ uint32_t pack_h(__half a, __half b) {
    return ((uint32_t)__half_as_ushort(b) << 16) | __half_as_ushort(a);
}
__device__ __forceinline__ uint32_t f2h2(float a, float b) {
    __half2 h = __floats2half2_rn(a, b);
    return *(uint32_t*)&h;
}
#define MMA16816(d, a0, a1, a2, a3, b0, b1)                                   \
    asm volatile(                                                             \
        "mma.sync.aligned.m16n8k16.row.col.f32.f16.f16.f32 "                  \
        "{%0,%1,%2,%3}, {%4,%5,%6,%7}, {%8,%9}, {%0,%1,%2,%3};"               \
        : "+f"((d)[0]), "+f"((d)[1]), "+f"((d)[2]), "+f"((d)[3])              \
        : "r"(a0), "r"(a1), "r"(a2), "r"(a3), "r"(b0), "r"(b1))

// =====================================================================
// fp32 -> fp16 convert
// =====================================================================
__global__ void cvt_fp16_kernel(const float* __restrict__ src,
                                __half* __restrict__ dst, int n4)
{
    int i = blockIdx.x * blockDim.x + threadIdx.x;
    if (i >= n4) return;
    float4 v = ((const float4*)src)[i];
    uint32_t* p = (uint32_t*)(dst + (size_t)i * 4);
    p[0] = pack_h(__float2half_rn(v.x), __float2half_rn(v.y));
    p[1] = pack_h(__float2half_rn(v.z), __float2half_rn(v.w));
}

// =====================================================================
// masked bias table: bf[h][i(64)][j(56)]
// =====================================================================
__global__ void bias_pre_kernel(const float* __restrict__ bias_table,
                                const int* __restrict__ rel_idx,
                                float* __restrict__ bf)
{
    int idx = blockIdx.x * 256 + threadIdx.x;
    if (idx >= NH * 64 * 56) return;
    const int j = idx % 56;
    const int i = (idx / 56) % 64;
    const int h = idx / (56 * 64);
    float v;
    if (j >= NTOK)      v = -1e30f;
    else if (i >= NTOK) v = 0.f;
    else                v = bias_table[rel_idx[i * NTOK + j] * NH + h];
    bf[idx] = v;
}

// =====================================================================
// FP16 GEMM, multi-tile CTAs: each CTA does TPC=4 consecutive M-tiles
// with ONE continuous 3-stage cp.async pipeline across tile boundaries.
// CTA tile 128x128, BK=64, 256 threads (8 warps 2x4), warp tile 64x32.
// =====================================================================
#define BKB 64
#define NKIT (KEFF / BKB)            // 8
#define TPC 4
#define NSTEP (TPC * NKIT)           // 32
#define STAGE_A (128 * BKB * 2)      // 16384
#define STAGE_BYTES (2 * STAGE_A)    // 32768
#define GEMM_SMEM (3 * STAGE_BYTES)  // 98304

__global__ void __launch_bounds__(256)
gemm_fp16(const __half* __restrict__ A,
          const __half* __restrict__ B,
          const float* __restrict__ bias,
          float* __restrict__ Cf,
          __half* __restrict__ Ch,
          int N, int out_mode)
{
    extern __shared__ char smem[];
    const uint32_t sb = smem_u32(smem);
    const int tid  = threadIdx.x;
    const int lane = tid & 31;
    const int wid  = tid >> 5;
    const int wm   = wid >> 2;
    const int wn   = wid & 3;

    const int mtile0 = blockIdx.y * TPC;
    const __half* Bg = B + (size_t)blockIdx.x * 128 * KEFF;

    const int lr = tid >> 3;
    const int lc = tid & 7;

    auto load_stage = [&](int step, int slot) {
        if (step >= NSTEP) return;
        const uint32_t base = sb + (uint32_t)slot * STAGE_BYTES;
        const __half* Ag = A + (size_t)(mtile0 + (step >> 3)) * 128 * KEFF;
        const int kof = (step & 7) * BKB;
#pragma unroll
        for (int i = 0; i < 4; i++) {
            const int r = lr + i * 32;
            const uint32_t so = (uint32_t)r * 128 + (uint32_t)((lc ^ (r & 7)) << 4);
            cp16(base + so,           Ag + (size_t)r * KEFF + kof + lc * 8);
            cp16(base + STAGE_A + so, Bg + (size_t)r * KEFF + kof + lc * 8);
        }
    };

    // ---- bias cache (columns fixed for this CTA/warp/thread) ----
    const int nBase = blockIdx.x * 128 + wn * 32;
    const int rr = lane >> 2;
    const int cc = (lane & 3) * 2;
    float bcx[4], bcy[4];
#pragma unroll
    for (int in = 0; in < 4; in++) {
        bcx[in] = bias[nBase + in * 8 + cc];
        bcy[in] = bias[nBase + in * 8 + cc + 1];
    }

    float acc[4][4][4];
#pragma unroll
    for (int a = 0; a < 4; a++)
#pragma unroll
        for (int b = 0; b < 4; b++)
#pragma unroll
            for (int c = 0; c < 4; c++) acc[a][b][c] = 0.f;

    load_stage(0, 0); asm volatile("cp.async.commit_group;" ::: "memory");
    load_stage(1, 1); asm volatile("cp.async.commit_group;" ::: "memory");

    const int rA0 = wm * 64 + (lane & 15);
    const int cAh = lane >> 4;
    const int rB0 = wn * 32 + (lane & 7);
    const int cBh = (lane >> 3) & 1;

    for (int s = 0; s < NSTEP; s++) {
        asm volatile("cp.async.wait_group 1;" ::: "memory");
        __syncthreads();
        load_stage(s + 2, (s + 2) % 3);
        asm volatile("cp.async.commit_group;" ::: "memory");

        const uint32_t base = sb + (uint32_t)(s % 3) * STAGE_BYTES;
#pragma unroll
        for (int kk = 0; kk < 4; kk++) {
            uint32_t afr[4][4];
#pragma unroll
            for (int im = 0; im < 4; im++) {
                const int r = rA0 + im * 16;
                const uint32_t addr = base + (uint32_t)r * 128 +
                    (uint32_t)(((2 * kk + cAh) ^ (r & 7)) << 4);
                asm volatile("ldmatrix.sync.aligned.m8n8.x4.shared.b16 {%0,%1,%2,%3}, [%4];"
                    : "=r"(afr[im][0]), "=r"(afr[im][1]), "=r"(afr[im][2]), "=r"(afr[im][3])
                    : "r"(addr));
            }
            uint32_t bfr[4][2];
#pragma unroll
            for (int in = 0; in < 4; in++) {
                const int r = rB0 + in * 8;
                const uint32_t addr = base + STAGE_A + (uint32_t)r * 128 +
                    (uint32_t)(((2 * kk + cBh) ^ (r & 7)) << 4);
                asm volatile("ldmatrix.sync.aligned.m8n8.x2.shared.b16 {%0,%1}, [%2];"
                    : "=r"(bfr[in][0]), "=r"(bfr[in][1]) : "r"(addr));
            }
#pragma unroll
            for (int im = 0; im < 4; im++)
#pragma unroll
                for (int in = 0; in < 4; in++)
                    MMA16816(acc[im][in], afr[im][0], afr[im][1], afr[im][2], afr[im][3],
                             bfr[in][0], bfr[in][1]);
        }

        // ---- per-tile epilogue (register-only; overlaps with prefetch) ----
        if ((s & (NKIT - 1)) == NKIT - 1) {
            const int mBase = (mtile0 + (s >> 3)) * 128 + wm * 64;
            if (!out_mode) {
#pragma unroll
                for (int im = 0; im < 4; im++)
#pragma unroll
                    for (int in = 0; in < 4; in++) {
                        const int row = mBase + im * 16 + rr;
                        const int col = nBase + in * 8 + cc;
                        *(float2*)(Cf + (size_t)row * N + col) =
                            make_float2(acc[im][in][0] + bcx[in], acc[im][in][1] + bcy[in]);
                        *(float2*)(Cf + (size_t)(row + 8) * N + col) =
                            make_float2(acc[im][in][2] + bcx[in], acc[im][in][3] + bcy[in]);
                        acc[im][in][0] = 0.f; acc[im][in][1] = 0.f;
                        acc[im][in][2] = 0.f; acc[im][in][3] = 0.f;
                    }
            } else {
#pragma unroll
                for (int im = 0; im < 4; im++)
#pragma unroll
                    for (int in = 0; in < 4; in++) {
                        const int row = mBase + im * 16 + rr;
                        const int col = nBase + in * 8 + cc;
                        *(uint32_t*)(Ch + (size_t)row * N + col) =
                            pack_h(__float2half_rn(acc[im][in][0] + bcx[in]),
                                   __float2half_rn(acc[im][in][1] + bcy[in]));
                        *(uint32_t*)(Ch + (size_t)(row + 8) * N + col) =
                            pack_h(__float2half_rn(acc[im][in][2] + bcx[in]),
                                   __float2half_rn(acc[im][in][3] + bcy[in]));
                        acc[im][in][0] = 0.f; acc[im][in][1] = 0.f;
                        acc[im][in][2] = 0.f; acc[im][in][3] = 0.f;
                    }
            }
        }
    }
}

// =====================================================================
// tensor-core windowed attention (unchanged from R12)
// =====================================================================
#define QOFF  0
#define KOFF  5120
#define VTOFF 10240
#define ATT_HALVES 14848   // 29696 bytes

__global__ void __launch_bounds__(256)
attn_mma_kernel(const __half* __restrict__ qkv,
                const float* __restrict__ bf,
                __half* __restrict__ outs)
{
    __shared__ __align__(16) __half sm[ATT_HALVES];

    const int b  = blockIdx.x;
    const int h0 = blockIdx.y * 2;
    const int tid = threadIdx.x;
    const uint32_t sb = smem_u32(sm);
    const size_t rowbase = (size_t)b * NTOK;

    {
        uint4 z = make_uint4(0, 0, 0, 0);
        for (int i = tid; i < ATT_HALVES / 8; i += 256)
            ((uint4*)sm)[i] = z;
    }
    __syncthreads();

    for (int it = tid; it < 784; it += 256) {
        const int c   = it & 3;
        const int r3  = it >> 2;
        const int row = r3 % 49;
        const int mh  = r3 / 49;
        const int head = mh & 1;
        const int mat  = mh >> 1;
        const __half* g = qkv + (rowbase + row) * (3 * CDIM) + mat * CDIM + (h0 + head) * HD + c * 8;
        const uint32_t dst = sb + (uint32_t)(mat * KOFF + head * 2560 + row * 40 + c * 8) * 2;
        cp16(dst, g);
    }
    for (int it = tid; it < 1568; it += 256) {
        const int c   = it & 15;
        const int r2  = it >> 4;
        const int row = r2 % 49;
        const int head = r2 / 49;
        const uint32_t v = *(const uint32_t*)(qkv + (rowbase + row) * (3 * CDIM) + 2 * CDIM + (h0 + head) * HD + 2 * c);
        __half* base = sm + VTOFF + head * 2304;
        base[(2 * c) * 72 + row]     = __ushort_as_half((unsigned short)(v & 0xFFFF));
        base[(2 * c + 1) * 72 + row] = __ushort_as_half((unsigned short)(v >> 16));
    }
    asm volatile("cp.async.commit_group;" ::: "memory");
    asm volatile("cp.async.wait_group 0;" ::: "memory");
    __syncthreads();

    const int lane = tid & 31;
    const int wid  = tid >> 5;
    const int head = wid >> 2;
    const int w    = wid & 3;
    const int g    = lane >> 2;
    const int t4   = lane & 3;

    const __half* Q  = sm + QOFF  + head * 2560;
    const __half* K  = sm + KOFF  + head * 2560;
    const __half* Vt = sm + VTOFF + head * 2304;

    float sc[7][4];
#pragma unroll
    for (int n = 0; n < 7; n++)
#pragma unroll
        for (int c = 0; c < 4; c++) sc[n][c] = 0.f;

#pragma unroll
    for (int kh = 0; kh < 2; kh++) {
        const int kc = 16 * kh + 2 * t4;
        const uint32_t a0 = *(const uint32_t*)&Q[(16 * w + g) * 40 + kc];
        const uint32_t a1 = *(const uint32_t*)&Q[(16 * w + g + 8) * 40 + kc];
        const uint32_t a2 = *(const uint32_t*)&Q[(16 * w + g) * 40 + kc + 8];
        const uint32_t a3 = *(const uint32_t*)&Q[(16 * w + g + 8) * 40 + kc + 8];
#pragma unroll
        for (int nt = 0; nt < 7; nt++) {
            const uint32_t b0 = *(const uint32_t*)&K[(8 * nt + g) * 40 + kc];
            const uint32_t b1 = *(const uint32_t*)&K[(8 * nt + g) * 40 + kc + 8];
            MMA16816(sc[nt], a0, a1, a2, a3, b0, b1);
        }
    }

    const float* bfr0 = bf + ((size_t)(h0 + head) * 64 + 16 * w + g) * 56;
    const float* bfr1 = bfr0 + 8 * 56;
    float m0 = -1e30f, m1 = -1e30f;
#pragma unroll
    for (int nt = 0; nt < 7; nt++) {
        const float2 bb0 = *(const float2*)&bfr0[8 * nt + 2 * t4];
        const float2 bb1 = *(const float2*)&bfr1[8 * nt + 2 * t4];
        sc[nt][0] = fmaf(sc[nt][0], 0.25f, bb0.x);
        sc[nt][1] = fmaf(sc[nt][1], 0.25f, bb0.y);
        sc[nt][2] = fmaf(sc[nt][2], 0.25f, bb1.x);
        sc[nt][3] = fmaf(sc[nt][3], 0.25f, bb1.y);
        m0 = fmaxf(m0, fmaxf(sc[nt][0], sc[nt][1]));
        m1 = fmaxf(m1, fmaxf(sc[nt][2], sc[nt][3]));
    }
    m0 = fmaxf(m0, __shfl_xor_sync(0xFFFFFFFF, m0, 1));
    m0 = fmaxf(m0, __shfl_xor_sync(0xFFFFFFFF, m0, 2));
    m1 = fmaxf(m1, __shfl_xor_sync(0xFFFFFFFF, m1, 1));
    m1 = fmaxf(m1, __shfl_xor_sync(0xFFFFFFFF, m1, 2));

    float s0 = 0.f, s1 = 0.f;
#pragma unroll
    for (int nt = 0; nt < 7; nt++) {
        sc[nt][0] = __expf(sc[nt][0] - m0); s0 += sc[nt][0];
        sc[nt][1] = __expf(sc[nt][1] - m0); s0 += sc[nt][1];
        sc[nt][2] = __expf(sc[nt][2] - m1); s1 += sc[nt][2];
        sc[nt][3] = __expf(sc[nt][3] - m1); s1 += sc[nt][3];
    }
    s0 += __shfl_xor_sync(0xFFFFFFFF, s0, 1);
    s0 += __shfl_xor_sync(0xFFFFFFFF, s0, 2);
    s1 += __shfl_xor_sync(0xFFFFFFFF, s1, 1);
    s1 += __shfl_xor_sync(0xFFFFFFFF, s1, 2);
    const float inv0 = 1.f / s0;
    const float inv1 = 1.f / s1;

    float oa[4][4];
#pragma unroll
    for (int n = 0; n < 4; n++)
#pragma unroll
        for (int c = 0; c < 4; c++) oa[n][c] = 0.f;

#pragma unroll
    for (int kt = 0; kt < 4; kt++) {
        const int n0 = 2 * kt, n1 = 2 * kt + 1;
        const uint32_t a0 = f2h2(sc[n0][0], sc[n0][1]);
        const uint32_t a1 = f2h2(sc[n0][2], sc[n0][3]);
        const uint32_t a2 = (n1 < 7) ? f2h2(sc[n1][0], sc[n1][1]) : 0u;
        const uint32_t a3 = (n1 < 7) ? f2h2(sc[n1][2], sc[n1][3]) : 0u;
        const int jc = 16 * kt + 2 * t4;
#pragma unroll
        for (int nt = 0; nt < 4; nt++) {
            const uint32_t b0 = *(const uint32_t*)&Vt[(8 * nt + g) * 72 + jc];
            const uint32_t b1 = *(const uint32_t*)&Vt[(8 * nt + g) * 72 + jc + 8];
            MMA16816(oa[nt], a0, a1, a2, a3, b0, b1);
        }
    }

    const int i0 = 16 * w + g, i1 = i0 + 8;
    const int dc = 2 * t4;
#pragma unroll
    for (int nt = 0; nt < 4; nt++) {
        const int d = 8 * nt + dc;
        if (i0 < NTOK)
            *(uint32_t*)(outs + (rowbase + i0) * CDIM + (h0 + head) * HD + d) =
                f2h2(oa[nt][0] * inv0, oa[nt][1] * inv0);
        if (i1 < NTOK)
            *(uint32_t*)(outs + (rowbase + i1) * CDIM + (h0 + head) * HD + d) =
                f2h2(oa[nt][2] * inv1, oa[nt][3] * inv1);
    }
}

// =====================================================================
// launch
// =====================================================================
static inline void launch_cvt(const float* src, __half* dst, size_t nelem) {
    const int n4 = (int)(nelem / 4);
    cvt_fp16_kernel<<<(n4 + 255) / 256, 256>>>(src, dst, n4);
}

extern "C" void kernel_launch(void* const* d_in, const int* in_sizes, int n_in,
                              void* d_out, int out_size)
{
    const float* x          = (const float*)d_in[0];
    const float* w_qkv      = (const float*)d_in[1];
    const float* b_qkv      = (const float*)d_in[2];
    const float* w_gamma    = (const float*)d_in[3];
    const float* b_gamma    = (const float*)d_in[4];
    const float* w_proj     = (const float*)d_in[5];
    const float* b_proj     = (const float*)d_in[6];
    const float* bias_table = (const float*)d_in[7];
    const int*   rel_idx    = (const int*)d_in[8];
    float* out = (float*)d_out;

    __half *X16, *QKV16, *ATT16, *G16, *W16;
    float* BF;
    cudaGetSymbolAddress((void**)&X16,   g_x16);
    cudaGetSymbolAddress((void**)&QKV16, g_qkv16);
    cudaGetSymbolAddress((void**)&ATT16, g_att16);
    cudaGetSymbolAddress((void**)&G16,   g_g16);
    cudaGetSymbolAddress((void**)&W16,   g_W16);
    cudaGetSymbolAddress((void**)&BF,    g_biasf);

    cudaFuncSetAttribute(gemm_fp16, cudaFuncAttributeMaxDynamicSharedMemorySize, GEMM_SMEM);

    // 0) masked bias table
    bias_pre_kernel<<<(NH * 64 * 56 + 255) / 256, 256>>>(bias_table, rel_idx, BF);

    // 1) qkv = x @ w_qkv^T + b_qkv   -> fp16 [100352, 1536]
    launch_cvt(x, X16, (size_t)M_TOT * CDIM);
    launch_cvt(w_qkv, W16, (size_t)3 * CDIM * CDIM);
    {
        dim3 grid(3 * CDIM / 128, M_TOT / 128 / TPC);   // 12 x 196
        gemm_fp16<<<grid, 256, GEMM_SMEM>>>(X16, W16, b_qkv, nullptr, QKV16, 3 * CDIM, 1);
    }
    // 2) tensor-core attention -> ATT16 fp16 [100352, 512]
    {
        dim3 grid(BATCH, NH / 2);
        attn_mma_kernel<<<grid, 256>>>(QKV16, BF, ATT16);
    }
    // 3) gamma -> G16 fp16
    launch_cvt(w_gamma, W16, (size_t)CDIM * CDIM);
    {
        dim3 grid(CDIM / 128, M_TOT / 128 / TPC);       // 4 x 196
        gemm_fp16<<<grid, 256, GEMM_SMEM>>>(ATT16, W16, b_gamma, nullptr, G16, CDIM, 1);
    }
    // 4) out = g @ w_proj^T + b_proj -> fp32 d_out
    launch_cvt(w_proj, W16, (size_t)CDIM * CDIM);
    {
        dim3 grid(CDIM / 128, M_TOT / 128 / TPC);       // 4 x 196
        gemm_fp16<<<grid, 256, GEMM_SMEM>>>(G16, W16, b_proj, out, nullptr, CDIM, 0);
    }
}

// round 14
// speedup vs baseline: 3.7114x; 1.2483x over previous
#include <cuda_runtime.h>
#include <cuda_fp16.h>
#include <cstdint>
#include <cstddef>

#define WIN 7
#define NTOK 49
#define NH 16
#define HD 32
#define CDIM 512
#define BATCH 2048
#define M_TOT (BATCH * NTOK)   // 100352 = 784 * 128
#define KEFF 512

// ---------------- scratch (static device globals; no allocations) ----------------
__device__ __half g_x16  [(size_t)M_TOT * CDIM];       // 103 MB
__device__ __half g_qkv16[(size_t)M_TOT * 3 * CDIM];   // 308 MB
__device__ __half g_att16[(size_t)M_TOT * CDIM];       // 103 MB
__device__ __half g_W16  [(size_t)3 * CDIM * CDIM];    // qkv weights fp16
__device__ __half g_WgT  [(size_t)CDIM * CDIM];        // w_gamma^T fp16
__device__ __half g_Wp16 [(size_t)CDIM * CDIM];        // w_proj fp16
__device__ __half g_Wf   [(size_t)CDIM * CDIM];        // fused W' = Wp@Wg fp16
__device__ float  g_bp   [CDIM];                       // fused bias b'
__device__ float  g_bzero[CDIM];                       // zeros (device globals are 0-init)
__device__ float  g_biasf[(size_t)NH * 64 * 56];       // masked attn bias table

// =====================================================================
// helpers
// =====================================================================
__device__ __forceinline__ uint32_t smem_u32(const void* p) {
    uint32_t a;
    asm("{ .reg .u64 t; cvta.to.shared.u64 t, %1; cvt.u32.u64 %0, t; }" : "=r"(a) : "l"(p));
    return a;
}
__device__ __forceinline__ void cp16(uint32_t s, const void* g) {
    asm volatile("cp.async.cg.shared.global [%0], [%1], 16;" :: "r"(s), "l"(g));
}
__device__ __forceinline__ uint32_t pack_h(__half a, __half b) {
    return ((uint32_t)__half_as_ushort(b) << 16) | __half_as_ushort(a);
}
__device__ __forceinline__ uint32_t f2h2(float a, float b) {
    __half2 h = __floats2half2_rn(a, b);
    return *(uint32_t*)&h;
}
#define MMA16816(d, a0, a1, a2, a3, b0, b1)                                   \
    asm volatile(                                                             \
        "mma.sync.aligned.m16n8k16.row.col.f32.f16.f16.f32 "                  \
        "{%0,%1,%2,%3}, {%4,%5,%6,%7}, {%8,%9}, {%0,%1,%2,%3};"               \
        : "+f"((d)[0]), "+f"((d)[1]), "+f"((d)[2]), "+f"((d)[3])              \
        : "r"(a0), "r"(a1), "r"(a2), "r"(a3), "r"(b0), "r"(b1))

// =====================================================================
// small prep kernels
// =====================================================================
__global__ void cvt_fp16_kernel(const float* __restrict__ src,
                                __half* __restrict__ dst, int n4)
{
    int i = blockIdx.x * blockDim.x + threadIdx.x;
    if (i >= n4) return;
    float4 v = ((const float4*)src)[i];
    uint32_t* p = (uint32_t*)(dst + (size_t)i * 4);
    p[0] = pack_h(__float2half_rn(v.x), __float2half_rn(v.y));
    p[1] = pack_h(__float2half_rn(v.z), __float2half_rn(v.w));
}

// transpose + cvt: dst[n, c] = fp16(src[c, n]), 512x512
__global__ void transpose_cvt_kernel(const float* __restrict__ src,
                                     __half* __restrict__ dst)
{
    __shared__ float tile[32][33];
    const int bx = blockIdx.x * 32, by = blockIdx.y * 32;
    const int tx = threadIdx.x, ty = threadIdx.y;
#pragma unroll
    for (int i = 0; i < 4; i++)
        tile[ty + 8 * i][tx] = src[(size_t)(by + ty + 8 * i) * CDIM + bx + tx];
    __syncthreads();
#pragma unroll
    for (int i = 0; i < 4; i++)
        dst[(size_t)(bx + ty + 8 * i) * CDIM + by + tx] =
            __float2half_rn(tile[tx][ty + 8 * i]);
}

// b'[i] = sum_k Wp[i,k] * bg[k] + bp[i]
__global__ void bprime_kernel(const float* __restrict__ Wp,
                              const float* __restrict__ bg,
                              const float* __restrict__ bp,
                              float* __restrict__ out)
{
    const int i = blockIdx.x * 64 + threadIdx.x;
    float s = 0.f;
    for (int k = 0; k < CDIM; k++) s = fmaf(Wp[(size_t)i * CDIM + k], bg[k], s);
    out[i] = s + bp[i];
}

// masked bias table: bf[h][i(64)][j(56)]
__global__ void bias_pre_kernel(const float* __restrict__ bias_table,
                                const int* __restrict__ rel_idx,
                                float* __restrict__ bf)
{
    int idx = blockIdx.x * 256 + threadIdx.x;
    if (idx >= NH * 64 * 56) return;
    const int j = idx % 56;
    const int i = (idx / 56) % 64;
    const int h = idx / (56 * 64);
    float v;
    if (j >= NTOK)      v = -1e30f;
    else if (i >= NTOK) v = 0.f;
    else                v = bias_table[rel_idx[i * NTOK + j] * NH + h];
    bf[idx] = v;
}

// =====================================================================
// FP16 GEMM, multi-tile CTAs (runtime tiles-per-CTA), continuous 3-stage
// cp.async pipeline.  CTA tile 128x128, BK=64, 256 thr, warp tile 64x32.
// =====================================================================
#define BKB 64
#define STAGE_A (128 * BKB * 2)      // 16384
#define STAGE_BYTES (2 * STAGE_A)    // 32768
#define GEMM_SMEM (3 * STAGE_BYTES)  // 98304

__global__ void __launch_bounds__(256)
gemm_fp16(const __half* __restrict__ A,
          const __half* __restrict__ B,
          const float* __restrict__ bias,
          float* __restrict__ Cf,
          __half* __restrict__ Ch,
          int N, int out_mode, int tpc)
{
    extern __shared__ char smem[];
    const uint32_t sb = smem_u32(smem);
    const int tid  = threadIdx.x;
    const int lane = tid & 31;
    const int wid  = tid >> 5;
    const int wm   = wid >> 2;
    const int wn   = wid & 3;

    const int mtile0 = blockIdx.y * tpc;
    const int nstep  = tpc * 8;
    const __half* Bg = B + (size_t)blockIdx.x * 128 * KEFF;

    const int lr = tid >> 3;
    const int lc = tid & 7;

    auto load_stage = [&](int step, int slot) {
        if (step >= nstep) return;
        const uint32_t base = sb + (uint32_t)slot * STAGE_BYTES;
        const __half* Ag = A + (size_t)(mtile0 + (step >> 3)) * 128 * KEFF;
        const int kof = (step & 7) * BKB;
#pragma unroll
        for (int i = 0; i < 4; i++) {
            const int r = lr + i * 32;
            const uint32_t so = (uint32_t)r * 128 + (uint32_t)((lc ^ (r & 7)) << 4);
            cp16(base + so,           Ag + (size_t)r * KEFF + kof + lc * 8);
            cp16(base + STAGE_A + so, Bg + (size_t)r * KEFF + kof + lc * 8);
        }
    };

    // bias cache (columns fixed for this CTA)
    const int nBase = blockIdx.x * 128 + wn * 32;
    const int rr = lane >> 2;
    const int cc = (lane & 3) * 2;
    float bcx[4], bcy[4];
#pragma unroll
    for (int in = 0; in < 4; in++) {
        bcx[in] = bias[nBase + in * 8 + cc];
        bcy[in] = bias[nBase + in * 8 + cc + 1];
    }

    float acc[4][4][4];
#pragma unroll
    for (int a = 0; a < 4; a++)
#pragma unroll
        for (int b = 0; b < 4; b++)
#pragma unroll
            for (int c = 0; c < 4; c++) acc[a][b][c] = 0.f;

    load_stage(0, 0); asm volatile("cp.async.commit_group;" ::: "memory");
    load_stage(1, 1); asm volatile("cp.async.commit_group;" ::: "memory");

    const int rA0 = wm * 64 + (lane & 15);
    const int cAh = lane >> 4;
    // paired B ldmatrix.x4 mapping (validated in R8)
    const int gB  = lane >> 3;            // 0..3
    const int rB0 = wn * 32 + (lane & 7);
    const int rBo = (gB >> 1) * 8;
    const int cBh = gB & 1;

    for (int s = 0; s < nstep; s++) {
        asm volatile("cp.async.wait_group 1;" ::: "memory");
        __syncthreads();
        load_stage(s + 2, (s + 2) % 3);
        asm volatile("cp.async.commit_group;" ::: "memory");

        const uint32_t base = sb + (uint32_t)(s % 3) * STAGE_BYTES;
#pragma unroll
        for (int kk = 0; kk < 4; kk++) {
            uint32_t afr[4][4];
#pragma unroll
            for (int im = 0; im < 4; im++) {
                const int r = rA0 + im * 16;
                const uint32_t addr = base + (uint32_t)r * 128 +
                    (uint32_t)(((2 * kk + cAh) ^ (r & 7)) << 4);
                asm volatile("ldmatrix.sync.aligned.m8n8.x4.shared.b16 {%0,%1,%2,%3}, [%4];"
                    : "=r"(afr[im][0]), "=r"(afr[im][1]), "=r"(afr[im][2]), "=r"(afr[im][3])
                    : "r"(addr));
            }
            uint32_t bfr[4][2];
#pragma unroll
            for (int ip = 0; ip < 2; ip++) {
                const int r = rB0 + ip * 16 + rBo;
                const uint32_t addr = base + STAGE_A + (uint32_t)r * 128 +
                    (uint32_t)(((2 * kk + cBh) ^ (r & 7)) << 4);
                asm volatile("ldmatrix.sync.aligned.m8n8.x4.shared.b16 {%0,%1,%2,%3}, [%4];"
                    : "=r"(bfr[2*ip][0]), "=r"(bfr[2*ip][1]),
                      "=r"(bfr[2*ip+1][0]), "=r"(bfr[2*ip+1][1])
                    : "r"(addr));
            }
#pragma unroll
            for (int im = 0; im < 4; im++)
#pragma unroll
                for (int in = 0; in < 4; in++)
                    MMA16816(acc[im][in], afr[im][0], afr[im][1], afr[im][2], afr[im][3],
                             bfr[in][0], bfr[in][1]);
        }

        // per-tile epilogue (register-only; overlaps with prefetch)
        if ((s & 7) == 7) {
            const int mBase = (mtile0 + (s >> 3)) * 128 + wm * 64;
            if (!out_mode) {
#pragma unroll
                for (int im = 0; im < 4; im++)
#pragma unroll
                    for (int in = 0; in < 4; in++) {
                        const int row = mBase + im * 16 + rr;
                        const int col = nBase + in * 8 + cc;
                        *(float2*)(Cf + (size_t)row * N + col) =
                            make_float2(acc[im][in][0] + bcx[in], acc[im][in][1] + bcy[in]);
                        *(float2*)(Cf + (size_t)(row + 8) * N + col) =
                            make_float2(acc[im][in][2] + bcx[in], acc[im][in][3] + bcy[in]);
                        acc[im][in][0] = 0.f; acc[im][in][1] = 0.f;
                        acc[im][in][2] = 0.f; acc[im][in][3] = 0.f;
                    }
            } else {
#pragma unroll
                for (int im = 0; im < 4; im++)
#pragma unroll
                    for (int in = 0; in < 4; in++) {
                        const int row = mBase + im * 16 + rr;
                        const int col = nBase + in * 8 + cc;
                        *(uint32_t*)(Ch + (size_t)row * N + col) =
                            pack_h(__float2half_rn(acc[im][in][0] + bcx[in]),
                                   __float2half_rn(acc[im][in][1] + bcy[in]));
                        *(uint32_t*)(Ch + (size_t)(row + 8) * N + col) =
                            pack_h(__float2half_rn(acc[im][in][2] + bcx[in]),
                                   __float2half_rn(acc[im][in][3] + bcy[in]));
                        acc[im][in][0] = 0.f; acc[im][in][1] = 0.f;
                        acc[im][in][2] = 0.f; acc[im][in][3] = 0.f;
                    }
            }
        }
    }
}

// =====================================================================
// tensor-core windowed attention (unchanged from R12)
// =====================================================================
#define QOFF  0
#define KOFF  5120
#define VTOFF 10240
#define ATT_HALVES 14848

__global__ void __launch_bounds__(256)
attn_mma_kernel(const __half* __restrict__ qkv,
                const float* __restrict__ bf,
                __half* __restrict__ outs)
{
    __shared__ __align__(16) __half sm[ATT_HALVES];

    const int b  = blockIdx.x;
    const int h0 = blockIdx.y * 2;
    const int tid = threadIdx.x;
    const uint32_t sb = smem_u32(sm);
    const size_t rowbase = (size_t)b * NTOK;

    {
        uint4 z = make_uint4(0, 0, 0, 0);
        for (int i = tid; i < ATT_HALVES / 8; i += 256)
            ((uint4*)sm)[i] = z;
    }
    __syncthreads();

    for (int it = tid; it < 784; it += 256) {
        const int c   = it & 3;
        const int r3  = it >> 2;
        const int row = r3 % 49;
        const int mh  = r3 / 49;
        const int head = mh & 1;
        const int mat  = mh >> 1;
        const __half* g = qkv + (rowbase + row) * (3 * CDIM) + mat * CDIM + (h0 + head) * HD + c * 8;
        const uint32_t dst = sb + (uint32_t)(mat * KOFF + head * 2560 + row * 40 + c * 8) * 2;
        cp16(dst, g);
    }
    for (int it = tid; it < 1568; it += 256) {
        const int c   = it & 15;
        const int r2  = it >> 4;
        const int row = r2 % 49;
        const int head = r2 / 49;
        const uint32_t v = *(const uint32_t*)(qkv + (rowbase + row) * (3 * CDIM) + 2 * CDIM + (h0 + head) * HD + 2 * c);
        __half* base = sm + VTOFF + head * 2304;
        base[(2 * c) * 72 + row]     = __ushort_as_half((unsigned short)(v & 0xFFFF));
        base[(2 * c + 1) * 72 + row] = __ushort_as_half((unsigned short)(v >> 16));
    }
    asm volatile("cp.async.commit_group;" ::: "memory");
    asm volatile("cp.async.wait_group 0;" ::: "memory");
    __syncthreads();

    const int lane = tid & 31;
    const int wid  = tid >> 5;
    const int head = wid >> 2;
    const int w    = wid & 3;
    const int g    = lane >> 2;
    const int t4   = lane & 3;

    const __half* Q  = sm + QOFF  + head * 2560;
    const __half* K  = sm + KOFF  + head * 2560;
    const __half* Vt = sm + VTOFF + head * 2304;

    float sc[7][4];
#pragma unroll
    for (int n = 0; n < 7; n++)
#pragma unroll
        for (int c = 0; c < 4; c++) sc[n][c] = 0.f;

#pragma unroll
    for (int kh = 0; kh < 2; kh++) {
        const int kc = 16 * kh + 2 * t4;
        const uint32_t a0 = *(const uint32_t*)&Q[(16 * w + g) * 40 + kc];
        const uint32_t a1 = *(const uint32_t*)&Q[(16 * w + g + 8) * 40 + kc];
        const uint32_t a2 = *(const uint32_t*)&Q[(16 * w + g) * 40 + kc + 8];
        const uint32_t a3 = *(const uint32_t*)&Q[(16 * w + g + 8) * 40 + kc + 8];
#pragma unroll
        for (int nt = 0; nt < 7; nt++) {
            const uint32_t b0 = *(const uint32_t*)&K[(8 * nt + g) * 40 + kc];
            const uint32_t b1 = *(const uint32_t*)&K[(8 * nt + g) * 40 + kc + 8];
            MMA16816(sc[nt], a0, a1, a2, a3, b0, b1);
        }
    }

    const float* bfr0 = bf + ((size_t)(h0 + head) * 64 + 16 * w + g) * 56;
    const float* bfr1 = bfr0 + 8 * 56;
    float m0 = -1e30f, m1 = -1e30f;
#pragma unroll
    for (int nt = 0; nt < 7; nt++) {
        const float2 bb0 = *(const float2*)&bfr0[8 * nt + 2 * t4];
        const float2 bb1 = *(const float2*)&bfr1[8 * nt + 2 * t4];
        sc[nt][0] = fmaf(sc[nt][0], 0.25f, bb0.x);
        sc[nt][1] = fmaf(sc[nt][1], 0.25f, bb0.y);
        sc[nt][2] = fmaf(sc[nt][2], 0.25f, bb1.x);
        sc[nt][3] = fmaf(sc[nt][3], 0.25f, bb1.y);
        m0 = fmaxf(m0, fmaxf(sc[nt][0], sc[nt][1]));
        m1 = fmaxf(m1, fmaxf(sc[nt][2], sc[nt][3]));
    }
    m0 = fmaxf(m0, __shfl_xor_sync(0xFFFFFFFF, m0, 1));
    m0 = fmaxf(m0, __shfl_xor_sync(0xFFFFFFFF, m0, 2));
    m1 = fmaxf(m1, __shfl_xor_sync(0xFFFFFFFF, m1, 1));
    m1 = fmaxf(m1, __shfl_xor_sync(0xFFFFFFFF, m1, 2));

    float s0 = 0.f, s1 = 0.f;
#pragma unroll
    for (int nt = 0; nt < 7; nt++) {
        sc[nt][0] = __expf(sc[nt][0] - m0); s0 += sc[nt][0];
        sc[nt][1] = __expf(sc[nt][1] - m0); s0 += sc[nt][1];
        sc[nt][2] = __expf(sc[nt][2] - m1); s1 += sc[nt][2];
        sc[nt][3] = __expf(sc[nt][3] - m1); s1 += sc[nt][3];
    }
    s0 += __shfl_xor_sync(0xFFFFFFFF, s0, 1);
    s0 += __shfl_xor_sync(0xFFFFFFFF, s0, 2);
    s1 += __shfl_xor_sync(0xFFFFFFFF, s1, 1);
    s1 += __shfl_xor_sync(0xFFFFFFFF, s1, 2);
    const float inv0 = 1.f / s0;
    const float inv1 = 1.f / s1;

    float oa[4][4];
#pragma unroll
    for (int n = 0; n < 4; n++)
#pragma unroll
        for (int c = 0; c < 4; c++) oa[n][c] = 0.f;

#pragma unroll
    for (int kt = 0; kt < 4; kt++) {
        const int n0 = 2 * kt, n1 = 2 * kt + 1;
        const uint32_t a0 = f2h2(sc[n0][0], sc[n0][1]);
        const uint32_t a1 = f2h2(sc[n0][2], sc[n0][3]);
        const uint32_t a2 = (n1 < 7) ? f2h2(sc[n1][0], sc[n1][1]) : 0u;
        const uint32_t a3 = (n1 < 7) ? f2h2(sc[n1][2], sc[n1][3]) : 0u;
        const int jc = 16 * kt + 2 * t4;
#pragma unroll
        for (int nt = 0; nt < 4; nt++) {
            const uint32_t b0 = *(const uint32_t*)&Vt[(8 * nt + g) * 72 + jc];
            const uint32_t b1 = *(const uint32_t*)&Vt[(8 * nt + g) * 72 + jc + 8];
            MMA16816(oa[nt], a0, a1, a2, a3, b0, b1);
        }
    }

    const int i0 = 16 * w + g, i1 = i0 + 8;
    const int dc = 2 * t4;
#pragma unroll
    for (int nt = 0; nt < 4; nt++) {
        const int d = 8 * nt + dc;
        if (i0 < NTOK)
            *(uint32_t*)(outs + (rowbase + i0) * CDIM + (h0 + head) * HD + d) =
                f2h2(oa[nt][0] * inv0, oa[nt][1] * inv0);
        if (i1 < NTOK)
            *(uint32_t*)(outs + (rowbase + i1) * CDIM + (h0 + head) * HD + d) =
                f2h2(oa[nt][2] * inv1, oa[nt][3] * inv1);
    }
}

// =====================================================================
// launch
// =====================================================================
static inline void launch_cvt(const float* src, __half* dst, size_t nelem) {
    const int n4 = (int)(nelem / 4);
    cvt_fp16_kernel<<<(n4 + 255) / 256, 256>>>(src, dst, n4);
}

extern "C" void kernel_launch(void* const* d_in, const int* in_sizes, int n_in,
                              void* d_out, int out_size)
{
    const float* x          = (const float*)d_in[0];
    const float* w_qkv      = (const float*)d_in[1];
    const float* b_qkv      = (const float*)d_in[2];
    const float* w_gamma    = (const float*)d_in[3];
    const float* b_gamma    = (const float*)d_in[4];
    const float* w_proj     = (const float*)d_in[5];
    const float* b_proj     = (const float*)d_in[6];
    const float* bias_table = (const float*)d_in[7];
    const int*   rel_idx    = (const int*)d_in[8];
    float* out = (float*)d_out;

    __half *X16, *QKV16, *ATT16, *W16, *WgT, *Wp16, *Wf;
    float *BF, *BP, *BZ;
    cudaGetSymbolAddress((void**)&X16,   g_x16);
    cudaGetSymbolAddress((void**)&QKV16, g_qkv16);
    cudaGetSymbolAddress((void**)&ATT16, g_att16);
    cudaGetSymbolAddress((void**)&W16,   g_W16);
    cudaGetSymbolAddress((void**)&WgT,   g_WgT);
    cudaGetSymbolAddress((void**)&Wp16,  g_Wp16);
    cudaGetSymbolAddress((void**)&Wf,    g_Wf);
    cudaGetSymbolAddress((void**)&BF,    g_biasf);
    cudaGetSymbolAddress((void**)&BP,    g_bp);
    cudaGetSymbolAddress((void**)&BZ,    g_bzero);

    cudaFuncSetAttribute(gemm_fp16, cudaFuncAttributeMaxDynamicSharedMemorySize, GEMM_SMEM);

    // 0) small preps: attn bias table; fused weight W' = Wp@Wg and b' = Wp bg + bp
    bias_pre_kernel<<<(NH * 64 * 56 + 255) / 256, 256>>>(bias_table, rel_idx, BF);
    {
        dim3 blk(32, 8), grd(CDIM / 32, CDIM / 32);
        transpose_cvt_kernel<<<grd, blk>>>(w_gamma, WgT);
    }
    launch_cvt(w_proj, Wp16, (size_t)CDIM * CDIM);
    bprime_kernel<<<CDIM / 64, 64>>>(w_proj, b_gamma, b_proj, BP);
    {
        // W'[512,512] = Wp @ Wg   via  A=Wp16, B=WgT  (tpc=1 -> 16 CTAs)
        dim3 grid(CDIM / 128, 4);
        gemm_fp16<<<grid, 256, GEMM_SMEM>>>(Wp16, WgT, BZ, nullptr, Wf, CDIM, 1, 1);
    }

    // 1) qkv = x @ w_qkv^T + b_qkv   -> fp16 [100352, 1536]
    launch_cvt(x, X16, (size_t)M_TOT * CDIM);
    launch_cvt(w_qkv, W16, (size_t)3 * CDIM * CDIM);
    {
        dim3 grid(3 * CDIM / 128, M_TOT / 128 / 4);    // 12 x 196
        gemm_fp16<<<grid, 256, GEMM_SMEM>>>(X16, W16, b_qkv, nullptr, QKV16, 3 * CDIM, 1, 4);
    }
    // 2) tensor-core attention -> ATT16 fp16 [100352, 512]
    {
        dim3 grid(BATCH, NH / 2);
        attn_mma_kernel<<<grid, 256>>>(QKV16, BF, ATT16);
    }
    // 3) out = att @ W'^T + b'  -> fp32 d_out   (gamma+proj fused)
    {
        dim3 grid(CDIM / 128, M_TOT / 128 / 4);        // 4 x 196
        gemm_fp16<<<grid, 256, GEMM_SMEM>>>(ATT16, Wf, BP, out, nullptr, CDIM, 0, 4);
    }
}

// round 15
// speedup vs baseline: 3.7551x; 1.0118x over previous
#include <cuda_runtime.h>
#include <cuda_fp16.h>
#include <cstdint>
#include <cstddef>

#define WIN 7
#define NTOK 49
#define NH 16
#define HD 32
#define CDIM 512
#define BATCH 2048
#define M_TOT (BATCH * NTOK)   // 100352 = 784 * 128
#define KEFF 512

// ---------------- scratch (static device globals; no allocations) ----------------
__device__ __half g_x16  [(size_t)M_TOT * CDIM];
__device__ __half g_qkv16[(size_t)M_TOT * 3 * CDIM];
__device__ __half g_att16[(size_t)M_TOT * CDIM];
__device__ __half g_W16  [(size_t)3 * CDIM * CDIM];
__device__ __half g_WgT  [(size_t)CDIM * CDIM];
__device__ __half g_Wp16 [(size_t)CDIM * CDIM];
__device__ __half g_Wf   [(size_t)CDIM * CDIM];
__device__ float  g_bp   [CDIM];
__device__ float  g_bzero[CDIM];
__device__ float  g_biasf[(size_t)NH * 64 * 56];

// =====================================================================
// helpers
// =====================================================================
__device__ __forceinline__ uint32_t smem_u32(const void* p) {
    uint32_t a;
    asm("{ .reg .u64 t; cvta.to.shared.u64 t, %1; cvt.u32.u64 %0, t; }" : "=r"(a) : "l"(p));
    return a;
}
__device__ __forceinline__ void cp16(uint32_t s, const void* g) {
    asm volatile("cp.async.cg.shared.global [%0], [%1], 16;" :: "r"(s), "l"(g));
}
__device__ __forceinline__ uint32_t pack_h(__half a, __half b) {
    return ((uint32_t)__half_as_ushort(b) << 16) | __half_as_ushort(a);
}
__device__ __forceinline__ uint32_t f2h2(float a, float b) {
    __half2 h = __floats2half2_rn(a, b);
    return *(uint32_t*)&h;
}
#define MMA16816(d, a0, a1, a2, a3, b0, b1)                                   \
    asm volatile(                                                             \
        "mma.sync.aligned.m16n8k16.row.col.f32.f16.f16.f32 "                  \
        "{%0,%1,%2,%3}, {%4,%5,%6,%7}, {%8,%9}, {%0,%1,%2,%3};"               \
        : "+f"((d)[0]), "+f"((d)[1]), "+f"((d)[2]), "+f"((d)[3])              \
        : "r"(a0), "r"(a1), "r"(a2), "r"(a3), "r"(b0), "r"(b1))

// =====================================================================
// small prep kernels
// =====================================================================
__global__ void cvt_fp16_kernel(const float* __restrict__ src,
                                __half* __restrict__ dst, int n4)
{
    int i = blockIdx.x * blockDim.x + threadIdx.x;
    if (i >= n4) return;
    float4 v = ((const float4*)src)[i];
    uint32_t* p = (uint32_t*)(dst + (size_t)i * 4);
    p[0] = pack_h(__float2half_rn(v.x), __float2half_rn(v.y));
    p[1] = pack_h(__float2half_rn(v.z), __float2half_rn(v.w));
}

// transpose + cvt: dst[n, c] = fp16(src[c, n]), 512x512
__global__ void transpose_cvt_kernel(const float* __restrict__ src,
                                     __half* __restrict__ dst)
{
    __shared__ float tile[32][33];
    const int bx = blockIdx.x * 32, by = blockIdx.y * 32;
    const int tx = threadIdx.x, ty = threadIdx.y;
#pragma unroll
    for (int i = 0; i < 4; i++)
        tile[ty + 8 * i][tx] = src[(size_t)(by + ty + 8 * i) * CDIM + bx + tx];
    __syncthreads();
#pragma unroll
    for (int i = 0; i < 4; i++)
        dst[(size_t)(bx + ty + 8 * i) * CDIM + by + tx] =
            __float2half_rn(tile[tx][ty + 8 * i]);
}

// b'[i] = sum_k Wp[i,k] * bg[k] + bp[i]  — one warp per output
__global__ void bprime_kernel(const float* __restrict__ Wp,
                              const float* __restrict__ bg,
                              const float* __restrict__ bp,
                              float* __restrict__ out)
{
    const int warp = (blockIdx.x * blockDim.x + threadIdx.x) >> 5;
    const int lane = threadIdx.x & 31;
    if (warp >= CDIM) return;
    float s = 0.f;
    for (int k = lane; k < CDIM; k += 32)
        s = fmaf(Wp[(size_t)warp * CDIM + k], bg[k], s);
#pragma unroll
    for (int o = 16; o > 0; o >>= 1)
        s += __shfl_xor_sync(0xFFFFFFFF, s, o);
    if (lane == 0) out[warp] = s + bp[warp];
}

// masked bias table: bf[h][i(64)][j(56)]
__global__ void bias_pre_kernel(const float* __restrict__ bias_table,
                                const int* __restrict__ rel_idx,
                                float* __restrict__ bf)
{
    int idx = blockIdx.x * 256 + threadIdx.x;
    if (idx >= NH * 64 * 56) return;
    const int j = idx % 56;
    const int i = (idx / 56) % 64;
    const int h = idx / (56 * 64);
    float v;
    if (j >= NTOK)      v = -1e30f;
    else if (i >= NTOK) v = 0.f;
    else                v = bias_table[rel_idx[i * NTOK + j] * NH + h];
    bf[idx] = v;
}

// =====================================================================
// FP16 GEMM, multi-tile CTAs, continuous 3-stage cp.async pipeline.
// CTA tile 128x128, BK=64, 256 thr, warp tile 64x32.
// =====================================================================
#define BKB 64
#define STAGE_A (128 * BKB * 2)      // 16384
#define STAGE_BYTES (2 * STAGE_A)    // 32768
#define GEMM_SMEM (3 * STAGE_BYTES)  // 98304

__global__ void __launch_bounds__(256)
gemm_fp16(const __half* __restrict__ A,
          const __half* __restrict__ B,
          const float* __restrict__ bias,
          float* __restrict__ Cf,
          __half* __restrict__ Ch,
          int N, int out_mode, int tpc)
{
    extern __shared__ char smem[];
    const uint32_t sb = smem_u32(smem);
    const int tid  = threadIdx.x;
    const int lane = tid & 31;
    const int wid  = tid >> 5;
    const int wm   = wid >> 2;
    const int wn   = wid & 3;

    const int mtile0 = blockIdx.y * tpc;
    const int nstep  = tpc * 8;
    const __half* Bg = B + (size_t)blockIdx.x * 128 * KEFF;

    const int lr = tid >> 3;
    const int lc = tid & 7;

    auto load_stage = [&](int step, int slot) {
        if (step >= nstep) return;
        const uint32_t base = sb + (uint32_t)slot * STAGE_BYTES;
        const __half* Ag = A + (size_t)(mtile0 + (step >> 3)) * 128 * KEFF;
        const int kof = (step & 7) * BKB;
#pragma unroll
        for (int i = 0; i < 4; i++) {
            const int r = lr + i * 32;
            const uint32_t so = (uint32_t)r * 128 + (uint32_t)((lc ^ (r & 7)) << 4);
            cp16(base + so,           Ag + (size_t)r * KEFF + kof + lc * 8);
            cp16(base + STAGE_A + so, Bg + (size_t)r * KEFF + kof + lc * 8);
        }
    };

    const int nBase = blockIdx.x * 128 + wn * 32;
    const int rr = lane >> 2;
    const int cc = (lane & 3) * 2;
    float bcx[4], bcy[4];
#pragma unroll
    for (int in = 0; in < 4; in++) {
        bcx[in] = bias[nBase + in * 8 + cc];
        bcy[in] = bias[nBase + in * 8 + cc + 1];
    }

    float acc[4][4][4];
#pragma unroll
    for (int a = 0; a < 4; a++)
#pragma unroll
        for (int b = 0; b < 4; b++)
#pragma unroll
            for (int c = 0; c < 4; c++) acc[a][b][c] = 0.f;

    load_stage(0, 0); asm volatile("cp.async.commit_group;" ::: "memory");
    load_stage(1, 1); asm volatile("cp.async.commit_group;" ::: "memory");

    const int rA0 = wm * 64 + (lane & 15);
    const int cAh = lane >> 4;
    const int gB  = lane >> 3;
    const int rB0 = wn * 32 + (lane & 7);
    const int rBo = (gB >> 1) * 8;
    const int cBh = gB & 1;

    for (int s = 0; s < nstep; s++) {
        asm volatile("cp.async.wait_group 1;" ::: "memory");
        __syncthreads();
        load_stage(s + 2, (s + 2) % 3);
        asm volatile("cp.async.commit_group;" ::: "memory");

        const uint32_t base = sb + (uint32_t)(s % 3) * STAGE_BYTES;
#pragma unroll
        for (int kk = 0; kk < 4; kk++) {
            uint32_t afr[4][4];
#pragma unroll
            for (int im = 0; im < 4; im++) {
                const int r = rA0 + im * 16;
                const uint32_t addr = base + (uint32_t)r * 128 +
                    (uint32_t)(((2 * kk + cAh) ^ (r & 7)) << 4);
                asm volatile("ldmatrix.sync.aligned.m8n8.x4.shared.b16 {%0,%1,%2,%3}, [%4];"
                    : "=r"(afr[im][0]), "=r"(afr[im][1]), "=r"(afr[im][2]), "=r"(afr[im][3])
                    : "r"(addr));
            }
            uint32_t bfr[4][2];
#pragma unroll
            for (int ip = 0; ip < 2; ip++) {
                const int r = rB0 + ip * 16 + rBo;
                const uint32_t addr = base + STAGE_A + (uint32_t)r * 128 +
                    (uint32_t)(((2 * kk + cBh) ^ (r & 7)) << 4);
                asm volatile("ldmatrix.sync.aligned.m8n8.x4.shared.b16 {%0,%1,%2,%3}, [%4];"
                    : "=r"(bfr[2*ip][0]), "=r"(bfr[2*ip][1]),
                      "=r"(bfr[2*ip+1][0]), "=r"(bfr[2*ip+1][1])
                    : "r"(addr));
            }
#pragma unroll
            for (int im = 0; im < 4; im++)
#pragma unroll
                for (int in = 0; in < 4; in++)
                    MMA16816(acc[im][in], afr[im][0], afr[im][1], afr[im][2], afr[im][3],
                             bfr[in][0], bfr[in][1]);
        }

        if ((s & 7) == 7) {
            const int mBase = (mtile0 + (s >> 3)) * 128 + wm * 64;
            if (!out_mode) {
#pragma unroll
                for (int im = 0; im < 4; im++)
#pragma unroll
                    for (int in = 0; in < 4; in++) {
                        const int row = mBase + im * 16 + rr;
                        const int col = nBase + in * 8 + cc;
                        *(float2*)(Cf + (size_t)row * N + col) =
                            make_float2(acc[im][in][0] + bcx[in], acc[im][in][1] + bcy[in]);
                        *(float2*)(Cf + (size_t)(row + 8) * N + col) =
                            make_float2(acc[im][in][2] + bcx[in], acc[im][in][3] + bcy[in]);
                        acc[im][in][0] = 0.f; acc[im][in][1] = 0.f;
                        acc[im][in][2] = 0.f; acc[im][in][3] = 0.f;
                    }
            } else {
#pragma unroll
                for (int im = 0; im < 4; im++)
#pragma unroll
                    for (int in = 0; in < 4; in++) {
                        const int row = mBase + im * 16 + rr;
                        const int col = nBase + in * 8 + cc;
                        *(uint32_t*)(Ch + (size_t)row * N + col) =
                            pack_h(__float2half_rn(acc[im][in][0] + bcx[in]),
                                   __float2half_rn(acc[im][in][1] + bcy[in]));
                        *(uint32_t*)(Ch + (size_t)(row + 8) * N + col) =
                            pack_h(__float2half_rn(acc[im][in][2] + bcx[in]),
                                   __float2half_rn(acc[im][in][3] + bcy[in]));
                        acc[im][in][0] = 0.f; acc[im][in][1] = 0.f;
                        acc[im][in][2] = 0.f; acc[im][in][3] = 0.f;
                    }
            }
        }
    }
}

// =====================================================================
// tensor-core windowed attention (unchanged)
// =====================================================================
#define QOFF  0
#define KOFF  5120
#define VTOFF 10240
#define ATT_HALVES 14848

__global__ void __launch_bounds__(256)
attn_mma_kernel(const __half* __restrict__ qkv,
                const float* __restrict__ bf,
                __half* __restrict__ outs)
{
    __shared__ __align__(16) __half sm[ATT_HALVES];

    const int b  = blockIdx.x;
    const int h0 = blockIdx.y * 2;
    const int tid = threadIdx.x;
    const uint32_t sb = smem_u32(sm);
    const size_t rowbase = (size_t)b * NTOK;

    {
        uint4 z = make_uint4(0, 0, 0, 0);
        for (int i = tid; i < ATT_HALVES / 8; i += 256)
            ((uint4*)sm)[i] = z;
    }
    __syncthreads();

    for (int it = tid; it < 784; it += 256) {
        const int c   = it & 3;
        const int r3  = it >> 2;
        const int row = r3 % 49;
        const int mh  = r3 / 49;
        const int head = mh & 1;
        const int mat  = mh >> 1;
        const __half* g = qkv + (rowbase + row) * (3 * CDIM) + mat * CDIM + (h0 + head) * HD + c * 8;
        const uint32_t dst = sb + (uint32_t)(mat * KOFF + head * 2560 + row * 40 + c * 8) * 2;
        cp16(dst, g);
    }
    for (int it = tid; it < 1568; it += 256) {
        const int c   = it & 15;
        const int r2  = it >> 4;
        const int row = r2 % 49;
        const int head = r2 / 49;
        const uint32_t v = *(const uint32_t*)(qkv + (rowbase + row) * (3 * CDIM) + 2 * CDIM + (h0 + head) * HD + 2 * c);
        __half* base = sm + VTOFF + head * 2304;
        base[(2 * c) * 72 + row]     = __ushort_as_half((unsigned short)(v & 0xFFFF));
        base[(2 * c + 1) * 72 + row] = __ushort_as_half((unsigned short)(v >> 16));
    }
    asm volatile("cp.async.commit_group;" ::: "memory");
    asm volatile("cp.async.wait_group 0;" ::: "memory");
    __syncthreads();

    const int lane = tid & 31;
    const int wid  = tid >> 5;
    const int head = wid >> 2;
    const int w    = wid & 3;
    const int g    = lane >> 2;
    const int t4   = lane & 3;

    const __half* Q  = sm + QOFF  + head * 2560;
    const __half* K  = sm + KOFF  + head * 2560;
    const __half* Vt = sm + VTOFF + head * 2304;

    float sc[7][4];
#pragma unroll
    for (int n = 0; n < 7; n++)
#pragma unroll
        for (int c = 0; c < 4; c++) sc[n][c] = 0.f;

#pragma unroll
    for (int kh = 0; kh < 2; kh++) {
        const int kc = 16 * kh + 2 * t4;
        const uint32_t a0 = *(const uint32_t*)&Q[(16 * w + g) * 40 + kc];
        const uint32_t a1 = *(const uint32_t*)&Q[(16 * w + g + 8) * 40 + kc];
        const uint32_t a2 = *(const uint32_t*)&Q[(16 * w + g) * 40 + kc + 8];
        const uint32_t a3 = *(const uint32_t*)&Q[(16 * w + g + 8) * 40 + kc + 8];
#pragma unroll
        for (int nt = 0; nt < 7; nt++) {
            const uint32_t b0 = *(const uint32_t*)&K[(8 * nt + g) * 40 + kc];
            const uint32_t b1 = *(const uint32_t*)&K[(8 * nt + g) * 40 + kc + 8];
            MMA16816(sc[nt], a0, a1, a2, a3, b0, b1);
        }
    }

    const float* bfr0 = bf + ((size_t)(h0 + head) * 64 + 16 * w + g) * 56;
    const float* bfr1 = bfr0 + 8 * 56;
    float m0 = -1e30f, m1 = -1e30f;
#pragma unroll
    for (int nt = 0; nt < 7; nt++) {
        const float2 bb0 = *(const float2*)&bfr0[8 * nt + 2 * t4];
        const float2 bb1 = *(const float2*)&bfr1[8 * nt + 2 * t4];
        sc[nt][0] = fmaf(sc[nt][0], 0.25f, bb0.x);
        sc[nt][1] = fmaf(sc[nt][1], 0.25f, bb0.y);
        sc[nt][2] = fmaf(sc[nt][2], 0.25f, bb1.x);
        sc[nt][3] = fmaf(sc[nt][3], 0.25f, bb1.y);
        m0 = fmaxf(m0, fmaxf(sc[nt][0], sc[nt][1]));
        m1 = fmaxf(m1, fmaxf(sc[nt][2], sc[nt][3]));
    }
    m0 = fmaxf(m0, __shfl_xor_sync(0xFFFFFFFF, m0, 1));
    m0 = fmaxf(m0, __shfl_xor_sync(0xFFFFFFFF, m0, 2));
    m1 = fmaxf(m1, __shfl_xor_sync(0xFFFFFFFF, m1, 1));
    m1 = fmaxf(m1, __shfl_xor_sync(0xFFFFFFFF, m1, 2));

    float s0 = 0.f, s1 = 0.f;
#pragma unroll
    for (int nt = 0; nt < 7; nt++) {
        sc[nt][0] = __expf(sc[nt][0] - m0); s0 += sc[nt][0];
        sc[nt][1] = __expf(sc[nt][1] - m0); s0 += sc[nt][1];
        sc[nt][2] = __expf(sc[nt][2] - m1); s1 += sc[nt][2];
        sc[nt][3] = __expf(sc[nt][3] - m1); s1 += sc[nt][3];
    }
    s0 += __shfl_xor_sync(0xFFFFFFFF, s0, 1);
    s0 += __shfl_xor_sync(0xFFFFFFFF, s0, 2);
    s1 += __shfl_xor_sync(0xFFFFFFFF, s1, 1);
    s1 += __shfl_xor_sync(0xFFFFFFFF, s1, 2);
    const float inv0 = 1.f / s0;
    const float inv1 = 1.f / s1;

    float oa[4][4];
#pragma unroll
    for (int n = 0; n < 4; n++)
#pragma unroll
        for (int c = 0; c < 4; c++) oa[n][c] = 0.f;

#pragma unroll
    for (int kt = 0; kt < 4; kt++) {
        const int n0 = 2 * kt, n1 = 2 * kt + 1;
        const uint32_t a0 = f2h2(sc[n0][0], sc[n0][1]);
        const uint32_t a1 = f2h2(sc[n0][2], sc[n0][3]);
        const uint32_t a2 = (n1 < 7) ? f2h2(sc[n1][0], sc[n1][1]) : 0u;
        const uint32_t a3 = (n1 < 7) ? f2h2(sc[n1][2], sc[n1][3]) : 0u;
        const int jc = 16 * kt + 2 * t4;
#pragma unroll
        for (int nt = 0; nt < 4; nt++) {
            const uint32_t b0 = *(const uint32_t*)&Vt[(8 * nt + g) * 72 + jc];
            const uint32_t b1 = *(const uint32_t*)&Vt[(8 * nt + g) * 72 + jc + 8];
            MMA16816(oa[nt], a0, a1, a2, a3, b0, b1);
        }
    }

    const int i0 = 16 * w + g, i1 = i0 + 8;
    const int dc = 2 * t4;
#pragma unroll
    for (int nt = 0; nt < 4; nt++) {
        const int d = 8 * nt + dc;
        if (i0 < NTOK)
            *(uint32_t*)(outs + (rowbase + i0) * CDIM + (h0 + head) * HD + d) =
                f2h2(oa[nt][0] * inv0, oa[nt][1] * inv0);
        if (i1 < NTOK)
            *(uint32_t*)(outs + (rowbase + i1) * CDIM + (h0 + head) * HD + d) =
                f2h2(oa[nt][2] * inv1, oa[nt][3] * inv1);
    }
}

// =====================================================================
// launch
// =====================================================================
static inline void launch_cvt(const float* src, __half* dst, size_t nelem) {
    const int n4 = (int)(nelem / 4);
    cvt_fp16_kernel<<<(n4 + 255) / 256, 256>>>(src, dst, n4);
}

extern "C" void kernel_launch(void* const* d_in, const int* in_sizes, int n_in,
                              void* d_out, int out_size)
{
    const float* x          = (const float*)d_in[0];
    const float* w_qkv      = (const float*)d_in[1];
    const float* b_qkv      = (const float*)d_in[2];
    const float* w_gamma    = (const float*)d_in[3];
    const float* b_gamma    = (const float*)d_in[4];
    const float* w_proj     = (const float*)d_in[5];
    const float* b_proj     = (const float*)d_in[6];
    const float* bias_table = (const float*)d_in[7];
    const int*   rel_idx    = (const int*)d_in[8];
    float* out = (float*)d_out;

    __half *X16, *QKV16, *ATT16, *W16, *WgT, *Wp16, *Wf;
    float *BF, *BP, *BZ;
    cudaGetSymbolAddress((void**)&X16,   g_x16);
    cudaGetSymbolAddress((void**)&QKV16, g_qkv16);
    cudaGetSymbolAddress((void**)&ATT16, g_att16);
    cudaGetSymbolAddress((void**)&W16,   g_W16);
    cudaGetSymbolAddress((void**)&WgT,   g_WgT);
    cudaGetSymbolAddress((void**)&Wp16,  g_Wp16);
    cudaGetSymbolAddress((void**)&Wf,    g_Wf);
    cudaGetSymbolAddress((void**)&BF,    g_biasf);
    cudaGetSymbolAddress((void**)&BP,    g_bp);
    cudaGetSymbolAddress((void**)&BZ,    g_bzero);

    cudaFuncSetAttribute(gemm_fp16, cudaFuncAttributeMaxDynamicSharedMemorySize, GEMM_SMEM);

    // 0) small preps
    bias_pre_kernel<<<(NH * 64 * 56 + 255) / 256, 256>>>(bias_table, rel_idx, BF);
    {
        dim3 blk(32, 8), grd(CDIM / 32, CDIM / 32);
        transpose_cvt_kernel<<<grd, blk>>>(w_gamma, WgT);
    }
    launch_cvt(w_proj, Wp16, (size_t)CDIM * CDIM);
    bprime_kernel<<<CDIM / 8, 256>>>(w_proj, b_gamma, b_proj, BP);   // 64 blocks x 8 warps
    {
        dim3 grid(CDIM / 128, 4);
        gemm_fp16<<<grid, 256, GEMM_SMEM>>>(Wp16, WgT, BZ, nullptr, Wf, CDIM, 1, 1);
    }

    // 1) qkv = x @ w_qkv^T + b_qkv   -> fp16 [100352, 1536]
    launch_cvt(x, X16, (size_t)M_TOT * CDIM);
    launch_cvt(w_qkv, W16, (size_t)3 * CDIM * CDIM);
    {
        dim3 grid(3 * CDIM / 128, M_TOT / 128 / 8);    // 12 x 98
        gemm_fp16<<<grid, 256, GEMM_SMEM>>>(X16, W16, b_qkv, nullptr, QKV16, 3 * CDIM, 1, 8);
    }
    // 2) tensor-core attention -> ATT16 fp16 [100352, 512]
    {
        dim3 grid(BATCH, NH / 2);
        attn_mma_kernel<<<grid, 256>>>(QKV16, BF, ATT16);
    }
    // 3) out = att @ W'^T + b'  -> fp32 d_out (gamma+proj fused)
    {
        dim3 grid(CDIM / 128, M_TOT / 128 / 8);        // 4 x 98
        gemm_fp16<<<grid, 256, GEMM_SMEM>>>(ATT16, Wf, BP, out, nullptr, CDIM, 0, 8);
    }
}

// round 16
// speedup vs baseline: 3.7995x; 1.0118x over previous
#include <cuda_runtime.h>
#include <cuda_fp16.h>
#include <cstdint>
#include <cstddef>

#define WIN 7
#define NTOK 49
#define NH 16
#define HD 32
#define CDIM 512
#define BATCH 2048
#define M_TOT (BATCH * NTOK)   // 100352 = 784 * 128
#define KEFF 512

// ---------------- scratch (static device globals; no allocations) ----------------
__device__ __half g_x16  [(size_t)M_TOT * CDIM];
__device__ __half g_qkv16[(size_t)M_TOT * 3 * CDIM];
__device__ __half g_att16[(size_t)M_TOT * CDIM];
__device__ __half g_W16  [(size_t)3 * CDIM * CDIM];
__device__ __half g_WgT  [(size_t)CDIM * CDIM];
__device__ __half g_Wp16 [(size_t)CDIM * CDIM];
__device__ __half g_Wf   [(size_t)CDIM * CDIM];
__device__ float  g_bp   [CDIM];
__device__ float  g_bzero[CDIM];
__device__ float  g_biasf[(size_t)NH * 64 * 56];

// =====================================================================
// helpers
// =====================================================================
__device__ __forceinline__ uint32_t smem_u32(const void* p) {
    uint32_t a;
    asm("{ .reg .u64 t; cvta.to.shared.u64 t, %1; cvt.u32.u64 %0, t; }" : "=r"(a) : "l"(p));
    return a;
}
__device__ __forceinline__ void cp16(uint32_t s, const void* g) {
    asm volatile("cp.async.cg.shared.global [%0], [%1], 16;" :: "r"(s), "l"(g));
}
__device__ __forceinline__ uint32_t pack_h(__half a, __half b) {
    return ((uint32_t)__half_as_ushort(b) << 16) | __half_as_ushort(a);
}
__device__ __forceinline__ uint32_t f2h2(float a, float b) {
    __half2 h = __floats2half2_rn(a, b);
    return *(uint32_t*)&h;
}
#define MMA16816(d, a0, a1, a2, a3, b0, b1)                                   \
    asm volatile(                                                             \
        "mma.sync.aligned.m16n8k16.row.col.f32.f16.f16.f32 "                  \
        "{%0,%1,%2,%3}, {%4,%5,%6,%7}, {%8,%9}, {%0,%1,%2,%3};"               \
        : "+f"((d)[0]), "+f"((d)[1]), "+f"((d)[2]), "+f"((d)[3])              \
        : "r"(a0), "r"(a1), "r"(a2), "r"(a3), "r"(b0), "r"(b1))

// =====================================================================
// merged prep kernel — block-range dispatch
//   [0, 50176)        cvt x        -> X16      (n4 = 12,845,056)
//   [50176, 50400)    bias table   -> biasf
//   [50400, 50656)    transpose    w_gamma -> WgT
//   [50656, 50912)    cvt w_proj   -> Wp16    (n4 = 65,536)
//   [50912, 51680)    cvt w_qkv    -> W16     (n4 = 196,608)
//   [51680, 51744)    bprime       -> bp
// =====================================================================
#define PB_X    50176
#define PB_BIAS 50400
#define PB_TR   50656
#define PB_CVP  50912
#define PB_CVQ  51680
#define PB_BPR  51744

__device__ __forceinline__ void cvt_body(const float* __restrict__ src,
                                         __half* __restrict__ dst,
                                         int i, int n4)
{
    if (i >= n4) return;
    float4 v = ((const float4*)src)[i];
    uint32_t* p = (uint32_t*)(dst + (size_t)i * 4);
    p[0] = pack_h(__float2half_rn(v.x), __float2half_rn(v.y));
    p[1] = pack_h(__float2half_rn(v.z), __float2half_rn(v.w));
}

__global__ void prep_kernel(const float* __restrict__ x,
                            const float* __restrict__ w_qkv,
                            const float* __restrict__ w_gamma,
                            const float* __restrict__ w_proj,
                            const float* __restrict__ b_gamma,
                            const float* __restrict__ b_proj,
                            const float* __restrict__ bias_table,
                            const int*   __restrict__ rel_idx,
                            __half* __restrict__ X16,
                            __half* __restrict__ W16,
                            __half* __restrict__ WgT,
                            __half* __restrict__ Wp16,
                            float* __restrict__ bp_out,
                            float* __restrict__ bf)
{
    __shared__ float tile[32][33];
    const int bid = blockIdx.x;
    const int tid = threadIdx.x;

    if (bid < PB_X) {
        cvt_body(x, X16, bid * 256 + tid, (M_TOT * CDIM) / 4);
    } else if (bid < PB_BIAS) {
        const int idx = (bid - PB_X) * 256 + tid;
        if (idx < NH * 64 * 56) {
            const int j = idx % 56;
            const int i = (idx / 56) % 64;
            const int h = idx / (56 * 64);
            float v;
            if (j >= NTOK)      v = -1e30f;
            else if (i >= NTOK) v = 0.f;
            else                v = bias_table[rel_idx[i * NTOK + j] * NH + h];
            bf[idx] = v;
        }
    } else if (bid < PB_TR) {
        const int blk = bid - PB_BIAS;
        const int bx = (blk & 15) * 32, by = (blk >> 4) * 32;
        const int tx = tid & 31, ty = tid >> 5;     // 32 x 8
#pragma unroll
        for (int i = 0; i < 4; i++)
            tile[ty + 8 * i][tx] = w_gamma[(size_t)(by + ty + 8 * i) * CDIM + bx + tx];
        __syncthreads();
#pragma unroll
        for (int i = 0; i < 4; i++)
            WgT[(size_t)(bx + ty + 8 * i) * CDIM + by + tx] =
                __float2half_rn(tile[tx][ty + 8 * i]);
    } else if (bid < PB_CVP) {
        cvt_body(w_proj, Wp16, (bid - PB_TR) * 256 + tid, (CDIM * CDIM) / 4);
    } else if (bid < PB_CVQ) {
        cvt_body(w_qkv, W16, (bid - PB_CVP) * 256 + tid, (3 * CDIM * CDIM) / 4);
    } else {
        // bprime: one warp per output row, float4-strided
        const int warp = (bid - PB_CVQ) * 8 + (tid >> 5);
        const int lane = tid & 31;
        if (warp < CDIM) {
            const float4* Wp4 = (const float4*)(w_proj + (size_t)warp * CDIM);
            const float4* bg4 = (const float4*)b_gamma;
            float s = 0.f;
#pragma unroll
            for (int i = 0; i < 4; i++) {
                const float4 wv = Wp4[lane + 32 * i];
                const float4 bv = bg4[lane + 32 * i];
                s = fmaf(wv.x, bv.x, s); s = fmaf(wv.y, bv.y, s);
                s = fmaf(wv.z, bv.z, s); s = fmaf(wv.w, bv.w, s);
            }
#pragma unroll
            for (int o = 16; o > 0; o >>= 1)
                s += __shfl_xor_sync(0xFFFFFFFF, s, o);
            if (lane == 0) bp_out[warp] = s + b_proj[warp];
        }
    }
}

// =====================================================================
// FP16 GEMM, multi-tile CTAs, continuous 3-stage cp.async pipeline.
// CTA tile 128x128, BK=64, 256 thr, warp tile 64x32.
// =====================================================================
#define BKB 64
#define STAGE_A (128 * BKB * 2)      // 16384
#define STAGE_BYTES (2 * STAGE_A)    // 32768
#define GEMM_SMEM (3 * STAGE_BYTES)  // 98304

__global__ void __launch_bounds__(256)
gemm_fp16(const __half* __restrict__ A,
          const __half* __restrict__ B,
          const float* __restrict__ bias,
          float* __restrict__ Cf,
          __half* __restrict__ Ch,
          int N, int out_mode, int tpc)
{
    extern __shared__ char smem[];
    const uint32_t sb = smem_u32(smem);
    const int tid  = threadIdx.x;
    const int lane = tid & 31;
    const int wid  = tid >> 5;
    const int wm   = wid >> 2;
    const int wn   = wid & 3;

    const int mtile0 = blockIdx.y * tpc;
    const int nstep  = tpc * 8;
    const __half* Bg = B + (size_t)blockIdx.x * 128 * KEFF;

    const int lr = tid >> 3;
    const int lc = tid & 7;

    auto load_stage = [&](int step, int slot) {
        if (step >= nstep) return;
        const uint32_t base = sb + (uint32_t)slot * STAGE_BYTES;
        const __half* Ag = A + (size_t)(mtile0 + (step >> 3)) * 128 * KEFF;
        const int kof = (step & 7) * BKB;
#pragma unroll
        for (int i = 0; i < 4; i++) {
            const int r = lr + i * 32;
            const uint32_t so = (uint32_t)r * 128 + (uint32_t)((lc ^ (r & 7)) << 4);
            cp16(base + so,           Ag + (size_t)r * KEFF + kof + lc * 8);
            cp16(base + STAGE_A + so, Bg + (size_t)r * KEFF + kof + lc * 8);
        }
    };

    const int nBase = blockIdx.x * 128 + wn * 32;
    const int rr = lane >> 2;
    const int cc = (lane & 3) * 2;
    float bcx[4], bcy[4];
#pragma unroll
    for (int in = 0; in < 4; in++) {
        bcx[in] = bias[nBase + in * 8 + cc];
        bcy[in] = bias[nBase + in * 8 + cc + 1];
    }

    float acc[4][4][4];
#pragma unroll
    for (int a = 0; a < 4; a++)
#pragma unroll
        for (int b = 0; b < 4; b++)
#pragma unroll
            for (int c = 0; c < 4; c++) acc[a][b][c] = 0.f;

    load_stage(0, 0); asm volatile("cp.async.commit_group;" ::: "memory");
    load_stage(1, 1); asm volatile("cp.async.commit_group;" ::: "memory");

    const int rA0 = wm * 64 + (lane & 15);
    const int cAh = lane >> 4;
    const int gB  = lane >> 3;
    const int rB0 = wn * 32 + (lane & 7);
    const int rBo = (gB >> 1) * 8;
    const int cBh = gB & 1;

    for (int s = 0; s < nstep; s++) {
        asm volatile("cp.async.wait_group 1;" ::: "memory");
        __syncthreads();
        load_stage(s + 2, (s + 2) % 3);
        asm volatile("cp.async.commit_group;" ::: "memory");

        const uint32_t base = sb + (uint32_t)(s % 3) * STAGE_BYTES;
#pragma unroll
        for (int kk = 0; kk < 4; kk++) {
            uint32_t afr[4][4];
#pragma unroll
            for (int im = 0; im < 4; im++) {
                const int r = rA0 + im * 16;
                const uint32_t addr = base + (uint32_t)r * 128 +
                    (uint32_t)(((2 * kk + cAh) ^ (r & 7)) << 4);
                asm volatile("ldmatrix.sync.aligned.m8n8.x4.shared.b16 {%0,%1,%2,%3}, [%4];"
                    : "=r"(afr[im][0]), "=r"(afr[im][1]), "=r"(afr[im][2]), "=r"(afr[im][3])
                    : "r"(addr));
            }
            uint32_t bfr[4][2];
#pragma unroll
            for (int ip = 0; ip < 2; ip++) {
                const int r = rB0 + ip * 16 + rBo;
                const uint32_t addr = base + STAGE_A + (uint32_t)r * 128 +
                    (uint32_t)(((2 * kk + cBh) ^ (r & 7)) << 4);
                asm volatile("ldmatrix.sync.aligned.m8n8.x4.shared.b16 {%0,%1,%2,%3}, [%4];"
                    : "=r"(bfr[2*ip][0]), "=r"(bfr[2*ip][1]),
                      "=r"(bfr[2*ip+1][0]), "=r"(bfr[2*ip+1][1])
                    : "r"(addr));
            }
#pragma unroll
            for (int im = 0; im < 4; im++)
#pragma unroll
                for (int in = 0; in < 4; in++)
                    MMA16816(acc[im][in], afr[im][0], afr[im][1], afr[im][2], afr[im][3],
                             bfr[in][0], bfr[in][1]);
        }

        if ((s & 7) == 7) {
            const int mBase = (mtile0 + (s >> 3)) * 128 + wm * 64;
            if (!out_mode) {
#pragma unroll
                for (int im = 0; im < 4; im++)
#pragma unroll
                    for (int in = 0; in < 4; in++) {
                        const int row = mBase + im * 16 + rr;
                        const int col = nBase + in * 8 + cc;
                        *(float2*)(Cf + (size_t)row * N + col) =
                            make_float2(acc[im][in][0] + bcx[in], acc[im][in][1] + bcy[in]);
                        *(float2*)(Cf + (size_t)(row + 8) * N + col) =
                            make_float2(acc[im][in][2] + bcx[in], acc[im][in][3] + bcy[in]);
                        acc[im][in][0] = 0.f; acc[im][in][1] = 0.f;
                        acc[im][in][2] = 0.f; acc[im][in][3] = 0.f;
                    }
            } else {
#pragma unroll
                for (int im = 0; im < 4; im++)
#pragma unroll
                    for (int in = 0; in < 4; in++) {
                        const int row = mBase + im * 16 + rr;
                        const int col = nBase + in * 8 + cc;
                        *(uint32_t*)(Ch + (size_t)row * N + col) =
                            pack_h(__float2half_rn(acc[im][in][0] + bcx[in]),
                                   __float2half_rn(acc[im][in][1] + bcy[in]));
                        *(uint32_t*)(Ch + (size_t)(row + 8) * N + col) =
                            pack_h(__float2half_rn(acc[im][in][2] + bcx[in]),
                                   __float2half_rn(acc[im][in][3] + bcy[in]));
                        acc[im][in][0] = 0.f; acc[im][in][1] = 0.f;
                        acc[im][in][2] = 0.f; acc[im][in][3] = 0.f;
                    }
            }
        }
    }
}

// =====================================================================
// tensor-core windowed attention (unchanged)
// =====================================================================
#define QOFF  0
#define KOFF  5120
#define VTOFF 10240
#define ATT_HALVES 14848

__global__ void __launch_bounds__(256)
attn_mma_kernel(const __half* __restrict__ qkv,
                const float* __restrict__ bf,
                __half* __restrict__ outs)
{
    __shared__ __align__(16) __half sm[ATT_HALVES];

    const int b  = blockIdx.x;
    const int h0 = blockIdx.y * 2;
    const int tid = threadIdx.x;
    const uint32_t sb = smem_u32(sm);
    const size_t rowbase = (size_t)b * NTOK;

    {
        uint4 z = make_uint4(0, 0, 0, 0);
        for (int i = tid; i < ATT_HALVES / 8; i += 256)
            ((uint4*)sm)[i] = z;
    }
    __syncthreads();

    for (int it = tid; it < 784; it += 256) {
        const int c   = it & 3;
        const int r3  = it >> 2;
        const int row = r3 % 49;
        const int mh  = r3 / 49;
        const int head = mh & 1;
        const int mat  = mh >> 1;
        const __half* g = qkv + (rowbase + row) * (3 * CDIM) + mat * CDIM + (h0 + head) * HD + c * 8;
        const uint32_t dst = sb + (uint32_t)(mat * KOFF + head * 2560 + row * 40 + c * 8) * 2;
        cp16(dst, g);
    }
    for (int it = tid; it < 1568; it += 256) {
        const int c   = it & 15;
        const int r2  = it >> 4;
        const int row = r2 % 49;
        const int head = r2 / 49;
        const uint32_t v = *(const uint32_t*)(qkv + (rowbase + row) * (3 * CDIM) + 2 * CDIM + (h0 + head) * HD + 2 * c);
        __half* base = sm + VTOFF + head * 2304;
        base[(2 * c) * 72 + row]     = __ushort_as_half((unsigned short)(v & 0xFFFF));
        base[(2 * c + 1) * 72 + row] = __ushort_as_half((unsigned short)(v >> 16));
    }
    asm volatile("cp.async.commit_group;" ::: "memory");
    asm volatile("cp.async.wait_group 0;" ::: "memory");
    __syncthreads();

    const int lane = tid & 31;
    const int wid  = tid >> 5;
    const int head = wid >> 2;
    const int w    = wid & 3;
    const int g    = lane >> 2;
    const int t4   = lane & 3;

    const __half* Q  = sm + QOFF  + head * 2560;
    const __half* K  = sm + KOFF  + head * 2560;
    const __half* Vt = sm + VTOFF + head * 2304;

    float sc[7][4];
#pragma unroll
    for (int n = 0; n < 7; n++)
#pragma unroll
        for (int c = 0; c < 4; c++) sc[n][c] = 0.f;

#pragma unroll
    for (int kh = 0; kh < 2; kh++) {
        const int kc = 16 * kh + 2 * t4;
        const uint32_t a0 = *(const uint32_t*)&Q[(16 * w + g) * 40 + kc];
        const uint32_t a1 = *(const uint32_t*)&Q[(16 * w + g + 8) * 40 + kc];
        const uint32_t a2 = *(const uint32_t*)&Q[(16 * w + g) * 40 + kc + 8];
        const uint32_t a3 = *(const uint32_t*)&Q[(16 * w + g + 8) * 40 + kc + 8];
#pragma unroll
        for (int nt = 0; nt < 7; nt++) {
            const uint32_t b0 = *(const uint32_t*)&K[(8 * nt + g) * 40 + kc];
            const uint32_t b1 = *(const uint32_t*)&K[(8 * nt + g) * 40 + kc + 8];
            MMA16816(sc[nt], a0, a1, a2, a3, b0, b1);
        }
    }

    const float* bfr0 = bf + ((size_t)(h0 + head) * 64 + 16 * w + g) * 56;
    const float* bfr1 = bfr0 + 8 * 56;
    float m0 = -1e30f, m1 = -1e30f;
#pragma unroll
    for (int nt = 0; nt < 7; nt++) {
        const float2 bb0 = *(const float2*)&bfr0[8 * nt + 2 * t4];
        const float2 bb1 = *(const float2*)&bfr1[8 * nt + 2 * t4];
        sc[nt][0] = fmaf(sc[nt][0], 0.25f, bb0.x);
        sc[nt][1] = fmaf(sc[nt][1], 0.25f, bb0.y);
        sc[nt][2] = fmaf(sc[nt][2], 0.25f, bb1.x);
        sc[nt][3] = fmaf(sc[nt][3], 0.25f, bb1.y);
        m0 = fmaxf(m0, fmaxf(sc[nt][0], sc[nt][1]));
        m1 = fmaxf(m1, fmaxf(sc[nt][2], sc[nt][3]));
    }
    m0 = fmaxf(m0, __shfl_xor_sync(0xFFFFFFFF, m0, 1));
    m0 = fmaxf(m0, __shfl_xor_sync(0xFFFFFFFF, m0, 2));
    m1 = fmaxf(m1, __shfl_xor_sync(0xFFFFFFFF, m1, 1));
    m1 = fmaxf(m1, __shfl_xor_sync(0xFFFFFFFF, m1, 2));

    float s0 = 0.f, s1 = 0.f;
#pragma unroll
    for (int nt = 0; nt < 7; nt++) {
        sc[nt][0] = __expf(sc[nt][0] - m0); s0 += sc[nt][0];
        sc[nt][1] = __expf(sc[nt][1] - m0); s0 += sc[nt][1];
        sc[nt][2] = __expf(sc[nt][2] - m1); s1 += sc[nt][2];
        sc[nt][3] = __expf(sc[nt][3] - m1); s1 += sc[nt][3];
    }
    s0 += __shfl_xor_sync(0xFFFFFFFF, s0, 1);
    s0 += __shfl_xor_sync(0xFFFFFFFF, s0, 2);
    s1 += __shfl_xor_sync(0xFFFFFFFF, s1, 1);
    s1 += __shfl_xor_sync(0xFFFFFFFF, s1, 2);
    const float inv0 = 1.f / s0;
    const float inv1 = 1.f / s1;

    float oa[4][4];
#pragma unroll
    for (int n = 0; n < 4; n++)
#pragma unroll
        for (int c = 0; c < 4; c++) oa[n][c] = 0.f;

#pragma unroll
    for (int kt = 0; kt < 4; kt++) {
        const int n0 = 2 * kt, n1 = 2 * kt + 1;
        const uint32_t a0 = f2h2(sc[n0][0], sc[n0][1]);
        const uint32_t a1 = f2h2(sc[n0][2], sc[n0][3]);
        const uint32_t a2 = (n1 < 7) ? f2h2(sc[n1][0], sc[n1][1]) : 0u;
        const uint32_t a3 = (n1 < 7) ? f2h2(sc[n1][2], sc[n1][3]) : 0u;
        const int jc = 16 * kt + 2 * t4;
#pragma unroll
        for (int nt = 0; nt < 4; nt++) {
            const uint32_t b0 = *(const uint32_t*)&Vt[(8 * nt + g) * 72 + jc];
            const uint32_t b1 = *(const uint32_t*)&Vt[(8 * nt + g) * 72 + jc + 8];
            MMA16816(oa[nt], a0, a1, a2, a3, b0, b1);
        }
    }

    const int i0 = 16 * w + g, i1 = i0 + 8;
    const int dc = 2 * t4;
#pragma unroll
    for (int nt = 0; nt < 4; nt++) {
        const int d = 8 * nt + dc;
        if (i0 < NTOK)
            *(uint32_t*)(outs + (rowbase + i0) * CDIM + (h0 + head) * HD + d) =
                f2h2(oa[nt][0] * inv0, oa[nt][1] * inv0);
        if (i1 < NTOK)
            *(uint32_t*)(outs + (rowbase + i1) * CDIM + (h0 + head) * HD + d) =
                f2h2(oa[nt][2] * inv1, oa[nt][3] * inv1);
    }
}

// =====================================================================
// launch
// =====================================================================
extern "C" void kernel_launch(void* const* d_in, const int* in_sizes, int n_in,
                              void* d_out, int out_size)
{
    const float* x          = (const float*)d_in[0];
    const float* w_qkv      = (const float*)d_in[1];
    const float* b_qkv      = (const float*)d_in[2];
    const float* w_gamma    = (const float*)d_in[3];
    const float* b_gamma    = (const float*)d_in[4];
    const float* w_proj     = (const float*)d_in[5];
    const float* b_proj     = (const float*)d_in[6];
    const float* bias_table = (const float*)d_in[7];
    const int*   rel_idx    = (const int*)d_in[8];
    float* out = (float*)d_out;

    __half *X16, *QKV16, *ATT16, *W16, *WgT, *Wp16, *Wf;
    float *BF, *BP, *BZ;
    cudaGetSymbolAddress((void**)&X16,   g_x16);
    cudaGetSymbolAddress((void**)&QKV16, g_qkv16);
    cudaGetSymbolAddress((void**)&ATT16, g_att16);
    cudaGetSymbolAddress((void**)&W16,   g_W16);
    cudaGetSymbolAddress((void**)&WgT,   g_WgT);
    cudaGetSymbolAddress((void**)&Wp16,  g_Wp16);
    cudaGetSymbolAddress((void**)&Wf,    g_Wf);
    cudaGetSymbolAddress((void**)&BF,    g_biasf);
    cudaGetSymbolAddress((void**)&BP,    g_bp);
    cudaGetSymbolAddress((void**)&BZ,    g_bzero);

    cudaFuncSetAttribute(gemm_fp16, cudaFuncAttributeMaxDynamicSharedMemorySize, GEMM_SMEM);

    // 0) merged preps: cvt x/w_qkv/w_proj, transpose w_gamma, bias table, b'
    prep_kernel<<<PB_BPR, 256>>>(x, w_qkv, w_gamma, w_proj, b_gamma, b_proj,
                                 bias_table, rel_idx,
                                 X16, W16, WgT, Wp16, BP, BF);

    // 0b) W'[512,512] = Wp @ Wg
    {
        dim3 grid(CDIM / 128, 4);
        gemm_fp16<<<grid, 256, GEMM_SMEM>>>(Wp16, WgT, BZ, nullptr, Wf, CDIM, 1, 1);
    }

    // 1) qkv = x @ w_qkv^T + b_qkv   -> fp16 [100352, 1536]
    {
        dim3 grid(3 * CDIM / 128, M_TOT / 128 / 8);    // 12 x 98
        gemm_fp16<<<grid, 256, GEMM_SMEM>>>(X16, W16, b_qkv, nullptr, QKV16, 3 * CDIM, 1, 8);
    }
    // 2) tensor-core attention -> ATT16 fp16 [100352, 512]
    {
        dim3 grid(BATCH, NH / 2);
        attn_mma_kernel<<<grid, 256>>>(QKV16, BF, ATT16);
    }
    // 3) out = att @ W'^T + b'  -> fp32 d_out (gamma+proj fused)
    {
        dim3 grid(CDIM / 128, M_TOT / 128 / 4);        // 4 x 196 (wave-balanced)
        gemm_fp16<<<grid, 256, GEMM_SMEM>>>(ATT16, Wf, BP, out, nullptr, CDIM, 0, 4);
    }
}